// round 2
// baseline (speedup 1.0000x reference)
#include <cuda_runtime.h>
#include <mma.h>

using namespace nvcuda;

// Problem constants: B=4, S=256, D_MODEL=2048, H=256, HEAD_DIM=8
#define TOKENS   1024           // B*S
#define DM       2048
#define NHEADS   256
#define HDIM     8

// Scratch (allocation-free rule: __device__ globals)
__device__ float g_q[TOKENS * DM];
__device__ float g_k[TOKENS * DM];
__device__ float g_v[TOKENS * DM];
__device__ float g_a[TOKENS * DM];

__device__ __forceinline__ float tf32_rna(float x) {
    float y;
    asm("cvt.rna.tf32.f32 %0, %1;" : "=f"(y) : "f"(x));
    return y;
}

// ---------------------------------------------------------------------------
// GEMM: C[M=1024, N=2048] = A[1024,2048] @ B[2048,2048] + bias[2048]
// TF32 wmma, BM=64 BN=128 BK=32, 256 threads = 8 warps (2x4), warp tile 32x32
// ---------------------------------------------------------------------------
#define BM 64
#define BN 128
#define BK 32
#define SA (BK + 4)   // 36
#define SB (BN + 4)   // 132
#define SC (BN + 4)   // 132

__global__ __launch_bounds__(256) void gemm_bias_tf32(
    const float* __restrict__ A, const float* __restrict__ B,
    const float* __restrict__ bias, float* __restrict__ C)
{
    __shared__ float smem[BM * SC];   // 64*132 = 8448 floats (33792 B); reused for epilogue
    float* As = smem;                 // BM x SA = 2304 floats
    float* Bs = smem + BM * SA;       // BK x SB = 4224 floats

    const int tid = threadIdx.x;
    const int bm = blockIdx.y * BM;
    const int bn = blockIdx.x * BN;
    const int warpId = tid >> 5;
    const int wr = warpId >> 2;       // 0..1
    const int wc = warpId & 3;        // 0..3

    wmma::fragment<wmma::accumulator, 16, 16, 8, float> acc[2][2];
#pragma unroll
    for (int i = 0; i < 2; i++)
#pragma unroll
        for (int j = 0; j < 2; j++)
            wmma::fill_fragment(acc[i][j], 0.0f);

    for (int kt = 0; kt < DM; kt += BK) {
        // Load A tile: 64x32 = 512 float4, 2 per thread
#pragma unroll
        for (int l = 0; l < 2; l++) {
            int i = tid + l * 256;
            int r = i >> 3, c4 = i & 7;
            float4 v = *reinterpret_cast<const float4*>(&A[(size_t)(bm + r) * DM + kt + c4 * 4]);
            float* dst = &As[r * SA + c4 * 4];
            dst[0] = tf32_rna(v.x); dst[1] = tf32_rna(v.y);
            dst[2] = tf32_rna(v.z); dst[3] = tf32_rna(v.w);
        }
        // Load B tile: 32x128 = 1024 float4, 4 per thread
#pragma unroll
        for (int l = 0; l < 4; l++) {
            int i = tid + l * 256;
            int r = i >> 5, c4 = i & 31;
            float4 v = *reinterpret_cast<const float4*>(&B[(size_t)(kt + r) * DM + bn + c4 * 4]);
            float* dst = &Bs[r * SB + c4 * 4];
            dst[0] = tf32_rna(v.x); dst[1] = tf32_rna(v.y);
            dst[2] = tf32_rna(v.z); dst[3] = tf32_rna(v.w);
        }
        __syncthreads();

#pragma unroll
        for (int kk = 0; kk < BK; kk += 8) {
            wmma::fragment<wmma::matrix_a, 16, 16, 8, wmma::precision::tf32, wmma::row_major> fa[2];
            wmma::fragment<wmma::matrix_b, 16, 16, 8, wmma::precision::tf32, wmma::row_major> fb[2];
#pragma unroll
            for (int i = 0; i < 2; i++)
                wmma::load_matrix_sync(fa[i], &As[(wr * 32 + i * 16) * SA + kk], SA);
#pragma unroll
            for (int j = 0; j < 2; j++)
                wmma::load_matrix_sync(fb[j], &Bs[kk * SB + wc * 32 + j * 16], SB);
#pragma unroll
            for (int i = 0; i < 2; i++)
#pragma unroll
                for (int j = 0; j < 2; j++)
                    wmma::mma_sync(acc[i][j], fa[i], fb[j], acc[i][j]);
        }
        __syncthreads();
    }

    // Epilogue: stage to smem, add bias, vectorized store
    float* Cs = smem;
#pragma unroll
    for (int i = 0; i < 2; i++)
#pragma unroll
        for (int j = 0; j < 2; j++)
            wmma::store_matrix_sync(&Cs[(wr * 32 + i * 16) * SC + wc * 32 + j * 16],
                                    acc[i][j], SC, wmma::mem_row_major);
    __syncthreads();

#pragma unroll
    for (int l = 0; l < 8; l++) {
        int i = tid + l * 256;          // 2048 float4 total
        int r = i >> 5, c4 = i & 31;
        float4 v = *reinterpret_cast<float4*>(&Cs[r * SC + c4 * 4]);
        float4 bb = *reinterpret_cast<const float4*>(&bias[bn + c4 * 4]);
        v.x += bb.x; v.y += bb.y; v.z += bb.z; v.w += bb.w;
        *reinterpret_cast<float4*>(&C[(size_t)(bm + r) * DM + bn + c4 * 4]) = v;
    }
}

// ---------------------------------------------------------------------------
// Per-token head-mixing attention.
// Token t: Q,K,V rows are [H=256, d=8]. scores[h,g] = (q_h . k_g)/sqrt(8),
// softmax over g, out[h,:] = attn[h,:] @ V.   1 block/token, thread = head.
// ---------------------------------------------------------------------------
__global__ __launch_bounds__(256) void attn_kernel()
{
    const int t = blockIdx.x;
    const int h = threadIdx.x;

    __shared__ float4 sk[NHEADS * 2];   // 256 heads x 8 floats
    __shared__ float4 sv[NHEADS * 2];

    const float4* qp = reinterpret_cast<const float4*>(&g_q[(size_t)t * DM]);
    const float4* kp = reinterpret_cast<const float4*>(&g_k[(size_t)t * DM]);
    const float4* vp = reinterpret_cast<const float4*>(&g_v[(size_t)t * DM]);

    sk[h * 2]     = kp[h * 2];
    sk[h * 2 + 1] = kp[h * 2 + 1];
    sv[h * 2]     = vp[h * 2];
    sv[h * 2 + 1] = vp[h * 2 + 1];
    float4 q0 = qp[h * 2];
    float4 q1 = qp[h * 2 + 1];
    __syncthreads();

    const float scale = 0.35355339059327373f;   // 1/sqrt(8)
    float m = -1e30f, lsum = 0.0f;
    float4 a0 = make_float4(0.f, 0.f, 0.f, 0.f);
    float4 a1 = make_float4(0.f, 0.f, 0.f, 0.f);

#pragma unroll 4
    for (int g = 0; g < NHEADS; g++) {
        float4 k0 = sk[g * 2];
        float4 k1 = sk[g * 2 + 1];
        float s = q0.x * k0.x + q0.y * k0.y + q0.z * k0.z + q0.w * k0.w
                + q1.x * k1.x + q1.y * k1.y + q1.z * k1.z + q1.w * k1.w;
        s *= scale;
        float nm = fmaxf(m, s);
        float p    = __expf(s - nm);
        float corr = __expf(m - nm);
        lsum = lsum * corr + p;
        float4 v0 = sv[g * 2];
        float4 v1 = sv[g * 2 + 1];
        a0.x = a0.x * corr + p * v0.x;  a0.y = a0.y * corr + p * v0.y;
        a0.z = a0.z * corr + p * v0.z;  a0.w = a0.w * corr + p * v0.w;
        a1.x = a1.x * corr + p * v1.x;  a1.y = a1.y * corr + p * v1.y;
        a1.z = a1.z * corr + p * v1.z;  a1.w = a1.w * corr + p * v1.w;
        m = nm;
    }

    float inv = 1.0f / lsum;
    float4* op = reinterpret_cast<float4*>(&g_a[(size_t)t * DM + h * HDIM]);
    a0.x *= inv; a0.y *= inv; a0.z *= inv; a0.w *= inv;
    a1.x *= inv; a1.y *= inv; a1.z *= inv; a1.w *= inv;
    op[0] = a0;
    op[1] = a1;
}

// ---------------------------------------------------------------------------
// Launch
// ---------------------------------------------------------------------------
extern "C" void kernel_launch(void* const* d_in, const int* in_sizes, int n_in,
                              void* d_out, int out_size)
{
    const float* x  = (const float*)d_in[0];
    // d_in[1] = phase_shift: mathematically cancels (cos^2+sin^2), unused.
    const float* Wq = (const float*)d_in[2];
    const float* bq = (const float*)d_in[3];
    const float* Wk = (const float*)d_in[4];
    const float* bk = (const float*)d_in[5];
    const float* Wv = (const float*)d_in[6];
    const float* bv = (const float*)d_in[7];
    const float* Wo = (const float*)d_in[8];
    const float* bo = (const float*)d_in[9];
    float* out = (float*)d_out;

    float *q_ptr, *k_ptr, *v_ptr, *a_ptr;
    cudaGetSymbolAddress((void**)&q_ptr, g_q);
    cudaGetSymbolAddress((void**)&k_ptr, g_k);
    cudaGetSymbolAddress((void**)&v_ptr, g_v);
    cudaGetSymbolAddress((void**)&a_ptr, g_a);

    dim3 ggrid(DM / BN, TOKENS / BM);   // (16, 16)
    gemm_bias_tf32<<<ggrid, 256>>>(x, Wq, bq, q_ptr);
    gemm_bias_tf32<<<ggrid, 256>>>(x, Wk, bk, k_ptr);
    gemm_bias_tf32<<<ggrid, 256>>>(x, Wv, bv, v_ptr);
    attn_kernel<<<TOKENS, 256>>>();
    gemm_bias_tf32<<<ggrid, 256>>>(a_ptr, Wo, bo, out);
}

// round 3
// speedup vs baseline: 1.1144x; 1.1144x over previous
#include <cuda_runtime.h>
#include <mma.h>
#include <cstdint>

using namespace nvcuda;

// Problem constants: B=4, S=256, D_MODEL=2048, H=256, HEAD_DIM=8
#define TOKENS   1024
#define DM       2048
#define NHEADS   256
#define HDIM     8

// Scratch (allocation-free rule: __device__ globals)
__device__ float g_q[TOKENS * DM];
__device__ float g_k[TOKENS * DM];
__device__ float g_v[TOKENS * DM];
__device__ float g_a[TOKENS * DM];

__device__ __forceinline__ float tf32_rna(float x) {
    float y;
    asm("cvt.rna.tf32.f32 %0, %1;" : "=f"(y) : "f"(x));
    return y;
}

// ---------------------------------------------------------------------------
// GEMM: C[1024,2048] = A[1024,2048] @ W[2048,2048] + bias
// TF32 wmma, BM=128 BN=128 BK=32, double-buffered cp.async, 256 threads.
// blockIdx.z selects which of up to 3 (W, bias, C) sets to use (QKV fusion).
// ---------------------------------------------------------------------------
#define BM 128
#define BN 128
#define BK 32
#define SA 36                  // A tile row stride (pad)
#define SB 132                 // B tile row stride (pad)
#define SC 132
#define A_STAGE (BM * SA)      // 4608 floats
#define B_STAGE (BK * SB)      // 4224 floats
#define STAGE   (A_STAGE + B_STAGE)   // 8832 floats
#define SMEM_FLOATS (2 * STAGE)       // 17664 floats = 70656 B (>= 128*132 epilogue)
#define NK (DM / BK)           // 64

__device__ __forceinline__ void cp16(uint32_t saddr, const void* gptr) {
    asm volatile("cp.async.cg.shared.global [%0], [%1], 16;\n" :: "r"(saddr), "l"(gptr));
}

extern "C" __global__ void __launch_bounds__(256, 2) gemm_qkv(
    const float* __restrict__ A,
    const float* __restrict__ W0, const float* __restrict__ W1, const float* __restrict__ W2,
    const float* __restrict__ b0, const float* __restrict__ b1, const float* __restrict__ b2,
    float* __restrict__ C0, float* __restrict__ C1, float* __restrict__ C2)
{
    extern __shared__ float sm[];

    const int z = blockIdx.z;
    const float* B    = (z == 0) ? W0 : (z == 1) ? W1 : W2;
    const float* bias = (z == 0) ? b0 : (z == 1) ? b1 : b2;
    float*       C    = (z == 0) ? C0 : (z == 1) ? C1 : C2;

    const int tid = threadIdx.x;
    const int bm = blockIdx.y * BM;
    const int bn = blockIdx.x * BN;
    const int warpId = tid >> 5;
    const int wr = warpId >> 2;   // 0..1  -> 64 rows each
    const int wc = warpId & 3;    // 0..3  -> 32 cols each

    wmma::fragment<wmma::accumulator, 16, 16, 8, float> acc[4][2];
#pragma unroll
    for (int i = 0; i < 4; i++)
#pragma unroll
        for (int j = 0; j < 2; j++)
            wmma::fill_fragment(acc[i][j], 0.0f);

    // ---- async tile loader ----
    auto load_stage = [&](int st, int kt) {
        float* As = sm + st * STAGE;
        float* Bs = As + A_STAGE;
#pragma unroll
        for (int l = 0; l < 4; l++) {               // A: 128x32 = 1024 float4
            int i = tid + l * 256;
            int r = i >> 3, c = (i & 7) * 4;
            cp16((uint32_t)__cvta_generic_to_shared(&As[r * SA + c]),
                 &A[(size_t)(bm + r) * DM + kt + c]);
        }
#pragma unroll
        for (int l = 0; l < 4; l++) {               // B: 32x128 = 1024 float4
            int i = tid + l * 256;
            int r = i >> 5, c = (i & 31) * 4;
            cp16((uint32_t)__cvta_generic_to_shared(&Bs[r * SB + c]),
                 &B[(size_t)(kt + r) * DM + bn + c]);
        }
        asm volatile("cp.async.commit_group;\n");
    };

    load_stage(0, 0);

    for (int it = 0; it < NK; it++) {
        if (it + 1 < NK) {
            load_stage((it + 1) & 1, (it + 1) * BK);
            asm volatile("cp.async.wait_group 1;\n");
        } else {
            asm volatile("cp.async.wait_group 0;\n");
        }
        __syncthreads();

        float* As = sm + (it & 1) * STAGE;
        float* Bs = As + A_STAGE;

#pragma unroll
        for (int kk = 0; kk < BK; kk += 8) {
            wmma::fragment<wmma::matrix_a, 16, 16, 8, wmma::precision::tf32, wmma::row_major> fa[4];
            wmma::fragment<wmma::matrix_b, 16, 16, 8, wmma::precision::tf32, wmma::row_major> fb[2];
#pragma unroll
            for (int i = 0; i < 4; i++) {
                wmma::load_matrix_sync(fa[i], &As[(wr * 64 + i * 16) * SA + kk], SA);
#pragma unroll
                for (int e = 0; e < fa[i].num_elements; e++) fa[i].x[e] = tf32_rna(fa[i].x[e]);
            }
#pragma unroll
            for (int j = 0; j < 2; j++) {
                wmma::load_matrix_sync(fb[j], &Bs[kk * SB + wc * 32 + j * 16], SB);
#pragma unroll
                for (int e = 0; e < fb[j].num_elements; e++) fb[j].x[e] = tf32_rna(fb[j].x[e]);
            }
#pragma unroll
            for (int i = 0; i < 4; i++)
#pragma unroll
                for (int j = 0; j < 2; j++)
                    wmma::mma_sync(acc[i][j], fa[i], fb[j], acc[i][j]);
        }
        __syncthreads();   // protect stage about to be overwritten next iter
    }

    // ---- epilogue: stage via smem, fused bias, float4 stores ----
    float* Cs = sm;
#pragma unroll
    for (int i = 0; i < 4; i++)
#pragma unroll
        for (int j = 0; j < 2; j++)
            wmma::store_matrix_sync(&Cs[(wr * 64 + i * 16) * SC + wc * 32 + j * 16],
                                    acc[i][j], SC, wmma::mem_row_major);
    __syncthreads();

#pragma unroll
    for (int l = 0; l < 16; l++) {                  // 128x128 = 4096 float4
        int i = tid + l * 256;
        int r = i >> 5, c = (i & 31) * 4;
        float4 v  = *reinterpret_cast<float4*>(&Cs[r * SC + c]);
        float4 bb = *reinterpret_cast<const float4*>(&bias[bn + c]);
        v.x += bb.x; v.y += bb.y; v.z += bb.z; v.w += bb.w;
        *reinterpret_cast<float4*>(&C[(size_t)(bm + r) * DM + bn + c]) = v;
    }
}

// ---------------------------------------------------------------------------
// Per-token head-mixing attention, no-running-max softmax.
// Scores = (q_h . k_g)/sqrt(8); |s| max ~5 over the whole problem, expf-safe.
// ---------------------------------------------------------------------------
__global__ __launch_bounds__(256) void attn_kernel()
{
    const int t = blockIdx.x;
    const int h = threadIdx.x;

    __shared__ float4 sk[NHEADS * 2];
    __shared__ float4 sv[NHEADS * 2];

    const float4* qp = reinterpret_cast<const float4*>(&g_q[(size_t)t * DM]);
    const float4* kp = reinterpret_cast<const float4*>(&g_k[(size_t)t * DM]);
    const float4* vp = reinterpret_cast<const float4*>(&g_v[(size_t)t * DM]);

    sk[h * 2]     = kp[h * 2];
    sk[h * 2 + 1] = kp[h * 2 + 1];
    sv[h * 2]     = vp[h * 2];
    sv[h * 2 + 1] = vp[h * 2 + 1];
    float4 q0 = qp[h * 2];
    float4 q1 = qp[h * 2 + 1];
    __syncthreads();

    const float scale = 0.35355339059327373f;   // 1/sqrt(8)
    float lsum = 0.0f;
    float4 a0 = make_float4(0.f, 0.f, 0.f, 0.f);
    float4 a1 = make_float4(0.f, 0.f, 0.f, 0.f);

#pragma unroll 8
    for (int g = 0; g < NHEADS; g++) {
        float4 k0 = sk[g * 2];
        float4 k1 = sk[g * 2 + 1];
        float s = q0.x * k0.x + q0.y * k0.y + q0.z * k0.z + q0.w * k0.w
                + q1.x * k1.x + q1.y * k1.y + q1.z * k1.z + q1.w * k1.w;
        float p = __expf(s * scale);
        lsum += p;
        float4 v0 = sv[g * 2];
        float4 v1 = sv[g * 2 + 1];
        a0.x += p * v0.x;  a0.y += p * v0.y;  a0.z += p * v0.z;  a0.w += p * v0.w;
        a1.x += p * v1.x;  a1.y += p * v1.y;  a1.z += p * v1.z;  a1.w += p * v1.w;
    }

    float inv = 1.0f / lsum;
    float4* op = reinterpret_cast<float4*>(&g_a[(size_t)t * DM + h * HDIM]);
    a0.x *= inv; a0.y *= inv; a0.z *= inv; a0.w *= inv;
    a1.x *= inv; a1.y *= inv; a1.z *= inv; a1.w *= inv;
    op[0] = a0;
    op[1] = a1;
}

// ---------------------------------------------------------------------------
// Launch
// ---------------------------------------------------------------------------
extern "C" void kernel_launch(void* const* d_in, const int* in_sizes, int n_in,
                              void* d_out, int out_size)
{
    const float* x  = (const float*)d_in[0];
    // d_in[1] = phase_shift: cos^2+sin^2 cancels analytically; unused.
    const float* Wq = (const float*)d_in[2];
    const float* bq = (const float*)d_in[3];
    const float* Wk = (const float*)d_in[4];
    const float* bk = (const float*)d_in[5];
    const float* Wv = (const float*)d_in[6];
    const float* bv = (const float*)d_in[7];
    const float* Wo = (const float*)d_in[8];
    const float* bo = (const float*)d_in[9];
    float* out = (float*)d_out;

    float *q_ptr, *k_ptr, *v_ptr, *a_ptr;
    cudaGetSymbolAddress((void**)&q_ptr, g_q);
    cudaGetSymbolAddress((void**)&k_ptr, g_k);
    cudaGetSymbolAddress((void**)&v_ptr, g_v);
    cudaGetSymbolAddress((void**)&a_ptr, g_a);

    const int smem_bytes = SMEM_FLOATS * sizeof(float);   // 70656
    cudaFuncSetAttribute(gemm_qkv, cudaFuncAttributeMaxDynamicSharedMemorySize, smem_bytes);

    dim3 gQKV(DM / BN, TOKENS / BM, 3);    // (16, 8, 3)
    gemm_qkv<<<gQKV, 256, smem_bytes>>>(x, Wq, Wk, Wv, bq, bk, bv, q_ptr, k_ptr, v_ptr);

    attn_kernel<<<TOKENS, 256>>>();

    dim3 gO(DM / BN, TOKENS / BM, 1);      // (16, 8, 1)
    gemm_qkv<<<gO, 256, smem_bytes>>>(a_ptr, Wo, Wo, Wo, bo, bo, bo, out, out, out);
}

// round 5
// speedup vs baseline: 1.9667x; 1.7649x over previous
#include <cuda_runtime.h>
#include <cstdint>

// Problem constants: B=4, S=256, D_MODEL=2048, H=256, HEAD_DIM=8
#define TOKENS   1024
#define DM       2048
#define NHEADS   256

// ---------------------------------------------------------------------------
// Scratch (__device__ globals; allocation-free rule)
// ---------------------------------------------------------------------------
__device__ float g_q[TOKENS * DM];
__device__ float g_k[TOKENS * DM];
__device__ float g_v[TOKENS * DM];
__device__ float g_a[TOKENS * DM];          // attn out (tf32-rna rounded)
__device__ float g_xr[TOKENS * DM];         // x, tf32-rna rounded
__device__ float g_wr[4 * DM * DM];         // Wq,Wk,Wv,Wo rna-rounded (layout unchanged [K,N])

__device__ __forceinline__ float tf32_rna(float x) {
    float y; asm("cvt.rna.tf32.f32 %0, %1;" : "=f"(y) : "f"(x)); return y;
}
__device__ __forceinline__ void cp16(uint32_t saddr, const void* gptr) {
    asm volatile("cp.async.cg.shared.global [%0], [%1], 16;\n" :: "r"(saddr), "l"(gptr));
}
__device__ __forceinline__ void mma_tf32(float* c, const uint32_t* a, const uint32_t* b) {
    asm volatile(
        "mma.sync.aligned.m16n8k8.row.col.f32.tf32.tf32.f32 "
        "{%0,%1,%2,%3}, {%4,%5,%6,%7}, {%8,%9}, {%0,%1,%2,%3};"
        : "+f"(c[0]), "+f"(c[1]), "+f"(c[2]), "+f"(c[3])
        : "r"(a[0]), "r"(a[1]), "r"(a[2]), "r"(a[3]), "r"(b[0]), "r"(b[1]));
}

// ---------------------------------------------------------------------------
// TF32 mma.sync GEMM: C[1024,2048] = A[1024,2048] @ W[2048,2048] + bias
// A row-major [M,K]; W row-major [K,N] (used directly as col-major B frags).
// CTA 128x128x32, 8 warps (2x4), warp tile 64x32, 3-stage cp.async ring.
// ---------------------------------------------------------------------------
#define BM 128
#define BN 128
#define BK 32
#define NS 3
#define NK (DM / BK)              // 64
#define SA 36                     // A smem row stride (floats): bank=(4g+t)%32 distinct
#define SB 136                    // B smem row stride (floats): bank=(8t+g)%32 distinct
#define A_FLOATS (BM * SA)        // 4608
#define B_FLOATS (BK * SB)        // 4352
#define STG_FLOATS (A_FLOATS + B_FLOATS)   // 8960
#define STG_BYTES  (STG_FLOATS * 4)        // 35840
#define GEMM_SMEM  (NS * STG_BYTES)        // 107520
#define SC 132                    // epilogue staging stride

extern "C" __global__ void __launch_bounds__(256, 2) gemm_mma(
    const float* __restrict__ A,
    const float* __restrict__ W0, const float* __restrict__ W1, const float* __restrict__ W2,
    const float* __restrict__ b0, const float* __restrict__ b1, const float* __restrict__ b2,
    float* __restrict__ C0, float* __restrict__ C1, float* __restrict__ C2)
{
    extern __shared__ char smem[];
    uint32_t sbase;
    asm("{ .reg .u64 t; cvta.to.shared.u64 t, %1; cvt.u32.u64 %0, t; }" : "=r"(sbase) : "l"(smem));

    const int z = blockIdx.z;
    const float* W    = (z == 0) ? W0 : (z == 1) ? W1 : W2;
    const float* bias = (z == 0) ? b0 : (z == 1) ? b1 : b2;
    float*       C    = (z == 0) ? C0 : (z == 1) ? C1 : C2;

    const int tid  = threadIdx.x;
    const int lane = tid & 31;
    const int g    = lane >> 2;        // 0..7
    const int t    = lane & 3;         // 0..3
    const int warp = tid >> 5;
    const int mrow0 = (warp >> 2) * 64;    // 0 or 64
    const int ncol0 = (warp & 3) * 32;     // 0,32,64,96
    const int bm = blockIdx.y * BM;
    const int bn = blockIdx.x * BN;

    float acc[4][4][4];
#pragma unroll
    for (int i = 0; i < 4; i++)
#pragma unroll
        for (int j = 0; j < 4; j++)
#pragma unroll
            for (int e = 0; e < 4; e++) acc[i][j][e] = 0.0f;

    // ---- async stage fill ----
    auto fill = [&](int it) {
        const uint32_t ab = sbase + (uint32_t)((it % NS) * STG_BYTES);
        const uint32_t bb = ab + A_FLOATS * 4;
        const int kt = it * BK;
        const float* Ag = A + (size_t)bm * DM + kt;
        const float* Wg = W + (size_t)kt * DM + bn;
#pragma unroll
        for (int l = 0; l < 4; l++) {              // A: 128x32 floats = 1024 x 16B
            int i = tid + l * 256;
            int r = i >> 3, c = i & 7;
            cp16(ab + (uint32_t)(r * (SA * 4) + c * 16), Ag + (size_t)r * DM + c * 4);
        }
#pragma unroll
        for (int l = 0; l < 4; l++) {              // B: 32x128 floats = 1024 x 16B
            int i = tid + l * 256;
            int r = i >> 5, c = i & 31;
            cp16(bb + (uint32_t)(r * (SB * 4) + c * 16), Wg + (size_t)r * DM + c * 4);
        }
        asm volatile("cp.async.commit_group;" ::: "memory");
    };

    fill(0);
    fill(1);

    for (int it = 0; it < NK; it++) {
        if (it < NK - 1) asm volatile("cp.async.wait_group 1;" ::: "memory");
        else             asm volatile("cp.async.wait_group 0;" ::: "memory");
        __syncthreads();

        const uint32_t* au = reinterpret_cast<const uint32_t*>(smem) + (it % NS) * STG_FLOATS;
        const uint32_t* bu = au + A_FLOATS;

#pragma unroll
        for (int kk = 0; kk < BK; kk += 8) {
            uint32_t af[4][4], bf[4][2];
#pragma unroll
            for (int mi = 0; mi < 4; mi++) {
                const int r0 = mrow0 + mi * 16 + g;
                af[mi][0] = au[(r0)     * SA + kk + t];
                af[mi][1] = au[(r0 + 8) * SA + kk + t];
                af[mi][2] = au[(r0)     * SA + kk + t + 4];
                af[mi][3] = au[(r0 + 8) * SA + kk + t + 4];
            }
#pragma unroll
            for (int nj = 0; nj < 4; nj++) {
                const int c = ncol0 + nj * 8 + g;
                bf[nj][0] = bu[(kk + t)     * SB + c];
                bf[nj][1] = bu[(kk + t + 4) * SB + c];
            }
#pragma unroll
            for (int mi = 0; mi < 4; mi++)
#pragma unroll
                for (int nj = 0; nj < 4; nj++)
                    mma_tf32(acc[mi][nj], af[mi], bf[nj]);
        }
        __syncthreads();
        if (it + 2 < NK) fill(it + 2);
    }

    // ---- epilogue: stage accumulators to smem, fused bias, coalesced stores ----
    __syncthreads();
    float* Cs = reinterpret_cast<float*>(smem);     // 128 x SC floats = 67584 B
#pragma unroll
    for (int mi = 0; mi < 4; mi++) {
        const int r0 = mrow0 + mi * 16 + g;
#pragma unroll
        for (int nj = 0; nj < 4; nj++) {
            const int c = ncol0 + nj * 8 + 2 * t;
            *reinterpret_cast<float2*>(&Cs[(r0)     * SC + c]) = make_float2(acc[mi][nj][0], acc[mi][nj][1]);
            *reinterpret_cast<float2*>(&Cs[(r0 + 8) * SC + c]) = make_float2(acc[mi][nj][2], acc[mi][nj][3]);
        }
    }
    __syncthreads();

#pragma unroll
    for (int l = 0; l < 16; l++) {                  // 128x128 = 4096 float4
        int i = tid + l * 256;
        int r = i >> 5, c = (i & 31) * 4;
        float4 v  = *reinterpret_cast<float4*>(&Cs[r * SC + c]);
        float4 bb = *reinterpret_cast<const float4*>(&bias[bn + c]);
        v.x += bb.x; v.y += bb.y; v.z += bb.z; v.w += bb.w;
        *reinterpret_cast<float4*>(&C[(size_t)(bm + r) * DM + bn + c]) = v;
    }
}

// ---------------------------------------------------------------------------
// Elementwise tf32-rna rounding pass
// ---------------------------------------------------------------------------
__global__ void round_kernel(const float* __restrict__ src, float* __restrict__ dst, int n4)
{
    int i = blockIdx.x * blockDim.x + threadIdx.x;
    if (i < n4) {
        float4 v = reinterpret_cast<const float4*>(src)[i];
        v.x = tf32_rna(v.x); v.y = tf32_rna(v.y); v.z = tf32_rna(v.z); v.w = tf32_rna(v.w);
        reinterpret_cast<float4*>(dst)[i] = v;
    }
}

// ---------------------------------------------------------------------------
// Per-token head-mixing attention (scores bounded, exp-safe), rna-rounded out.
// ---------------------------------------------------------------------------
__global__ void __launch_bounds__(256) attn_kernel()
{
    const int tk = blockIdx.x;
    const int h  = threadIdx.x;

    __shared__ float4 sk[NHEADS * 2];
    __shared__ float4 sv[NHEADS * 2];

    const float4* qp = reinterpret_cast<const float4*>(&g_q[(size_t)tk * DM]);
    const float4* kp = reinterpret_cast<const float4*>(&g_k[(size_t)tk * DM]);
    const float4* vp = reinterpret_cast<const float4*>(&g_v[(size_t)tk * DM]);

    sk[h * 2]     = kp[h * 2];
    sk[h * 2 + 1] = kp[h * 2 + 1];
    sv[h * 2]     = vp[h * 2];
    sv[h * 2 + 1] = vp[h * 2 + 1];
    float4 q0 = qp[h * 2];
    float4 q1 = qp[h * 2 + 1];
    __syncthreads();

    const float scale = 0.35355339059327373f;   // 1/sqrt(8)
    float lsum = 0.0f;
    float4 a0 = make_float4(0.f, 0.f, 0.f, 0.f);
    float4 a1 = make_float4(0.f, 0.f, 0.f, 0.f);

#pragma unroll 8
    for (int gg = 0; gg < NHEADS; gg++) {
        float4 k0 = sk[gg * 2];
        float4 k1 = sk[gg * 2 + 1];
        float s = q0.x * k0.x + q0.y * k0.y + q0.z * k0.z + q0.w * k0.w
                + q1.x * k1.x + q1.y * k1.y + q1.z * k1.z + q1.w * k1.w;
        float p = __expf(s * scale);
        lsum += p;
        float4 v0 = sv[gg * 2];
        float4 v1 = sv[gg * 2 + 1];
        a0.x += p * v0.x;  a0.y += p * v0.y;  a0.z += p * v0.z;  a0.w += p * v0.w;
        a1.x += p * v1.x;  a1.y += p * v1.y;  a1.z += p * v1.z;  a1.w += p * v1.w;
    }

    float inv = 1.0f / lsum;
    float4* op = reinterpret_cast<float4*>(&g_a[(size_t)tk * DM + h * 8]);
    a0.x = tf32_rna(a0.x * inv); a0.y = tf32_rna(a0.y * inv);
    a0.z = tf32_rna(a0.z * inv); a0.w = tf32_rna(a0.w * inv);
    a1.x = tf32_rna(a1.x * inv); a1.y = tf32_rna(a1.y * inv);
    a1.z = tf32_rna(a1.z * inv); a1.w = tf32_rna(a1.w * inv);
    op[0] = a0;
    op[1] = a1;
}

// ---------------------------------------------------------------------------
// Launch
// ---------------------------------------------------------------------------
extern "C" void kernel_launch(void* const* d_in, const int* in_sizes, int n_in,
                              void* d_out, int out_size)
{
    const float* x  = (const float*)d_in[0];
    // d_in[1] = phase_shift: cos^2+sin^2 cancels analytically; unused.
    const float* Wq = (const float*)d_in[2];
    const float* bq = (const float*)d_in[3];
    const float* Wk = (const float*)d_in[4];
    const float* bk = (const float*)d_in[5];
    const float* Wv = (const float*)d_in[6];
    const float* bv = (const float*)d_in[7];
    const float* Wo = (const float*)d_in[8];
    const float* bo = (const float*)d_in[9];
    float* out = (float*)d_out;

    float *q_p, *k_p, *v_p, *a_p, *xr_p, *wr_p;
    cudaGetSymbolAddress((void**)&q_p,  g_q);
    cudaGetSymbolAddress((void**)&k_p,  g_k);
    cudaGetSymbolAddress((void**)&v_p,  g_v);
    cudaGetSymbolAddress((void**)&a_p,  g_a);
    cudaGetSymbolAddress((void**)&xr_p, g_xr);
    cudaGetSymbolAddress((void**)&wr_p, g_wr);

    cudaFuncSetAttribute(gemm_mma, cudaFuncAttributeMaxDynamicSharedMemorySize, GEMM_SMEM);

    const size_t WSZ = (size_t)DM * DM;
    const int nx4 = TOKENS * DM / 4, nw4 = (int)(WSZ / 4);
    round_kernel<<<(nx4 + 255) / 256, 256>>>(x, xr_p, nx4);
    round_kernel<<<(nw4 + 255) / 256, 256>>>(Wq, wr_p,           nw4);
    round_kernel<<<(nw4 + 255) / 256, 256>>>(Wk, wr_p + WSZ,     nw4);
    round_kernel<<<(nw4 + 255) / 256, 256>>>(Wv, wr_p + 2 * WSZ, nw4);
    round_kernel<<<(nw4 + 255) / 256, 256>>>(Wo, wr_p + 3 * WSZ, nw4);

    dim3 gQKV(DM / BN, TOKENS / BM, 3);   // (16, 8, 3)
    gemm_mma<<<gQKV, 256, GEMM_SMEM>>>(xr_p,
        wr_p, wr_p + WSZ, wr_p + 2 * WSZ,
        bq, bk, bv, q_p, k_p, v_p);

    attn_kernel<<<TOKENS, 256>>>();

    dim3 gO(DM / BN, TOKENS / BM, 1);     // (16, 8, 1)
    gemm_mma<<<gO, 256, GEMM_SMEM>>>(a_p,
        wr_p + 3 * WSZ, wr_p + 3 * WSZ, wr_p + 3 * WSZ,
        bo, bo, bo, out, out, out);
}

// round 6
// speedup vs baseline: 2.0234x; 1.0288x over previous
#include <cuda_runtime.h>
#include <cstdint>

// Problem constants: B=4, S=256, D_MODEL=2048, H=256, HEAD_DIM=8
#define TOKENS   1024
#define DM       2048
#define NHEADS   256

// ---------------------------------------------------------------------------
// Scratch (__device__ globals; allocation-free rule)
// ---------------------------------------------------------------------------
__device__ float g_q[TOKENS * DM];
__device__ float g_k[TOKENS * DM];
__device__ float g_v[TOKENS * DM];
__device__ float g_a[TOKENS * DM];          // attn out (tf32-rna rounded)
__device__ float g_xr[TOKENS * DM];         // x, tf32-rna rounded
__device__ float g_wr[4 * DM * DM];         // Wq,Wk,Wv,Wo rna-rounded ([K,N] layout)

__device__ __forceinline__ float tf32_rna(float x) {
    float y; asm("cvt.rna.tf32.f32 %0, %1;" : "=f"(y) : "f"(x)); return y;
}
__device__ __forceinline__ void cp16(uint32_t saddr, const void* gptr) {
    asm volatile("cp.async.cg.shared.global [%0], [%1], 16;\n" :: "r"(saddr), "l"(gptr));
}
__device__ __forceinline__ void mma_tf32(float* c, const uint32_t* a, const uint32_t* b) {
    asm volatile(
        "mma.sync.aligned.m16n8k8.row.col.f32.tf32.tf32.f32 "
        "{%0,%1,%2,%3}, {%4,%5,%6,%7}, {%8,%9}, {%0,%1,%2,%3};"
        : "+f"(c[0]), "+f"(c[1]), "+f"(c[2]), "+f"(c[3])
        : "r"(a[0]), "r"(a[1]), "r"(a[2]), "r"(a[3]), "r"(b[0]), "r"(b[1]));
}

// packed f32x2 helpers (base-ISA sm_100+; not 'a'-gated)
__device__ __forceinline__ uint64_t pk2(float lo, float hi) {
    uint64_t r; asm("mov.b64 %0, {%1, %2};" : "=l"(r) : "f"(lo), "f"(hi)); return r;
}
__device__ __forceinline__ void up2(uint64_t v, float& lo, float& hi) {
    asm("mov.b64 {%0, %1}, %2;" : "=f"(lo), "=f"(hi) : "l"(v));
}
__device__ __forceinline__ uint64_t fma2(uint64_t a, uint64_t b, uint64_t c) {
    uint64_t d; asm("fma.rn.f32x2 %0, %1, %2, %3;" : "=l"(d) : "l"(a), "l"(b), "l"(c)); return d;
}
__device__ __forceinline__ uint64_t mul2(uint64_t a, uint64_t b) {
    uint64_t d; asm("mul.rn.f32x2 %0, %1, %2;" : "=l"(d) : "l"(a), "l"(b)); return d;
}

// ---------------------------------------------------------------------------
// TF32 mma.sync GEMM: C[1024,2048] = A @ W + bias.  Template BMt: 128 or 64.
// 8 warps (2x4), warp tile (BMt/2)x32, 3-stage cp.async ring, 1 bar/iter.
// ---------------------------------------------------------------------------
#define BN 128
#define BK 32
#define NS 3
#define NK (DM / BK)              // 64
#define SA 36                     // A smem row stride (floats)
#define SB 136                    // B smem row stride (floats)
#define B_FLOATS (BK * SB)        // 4352
#define SC 132                    // epilogue staging stride

template <int BMt>
__global__ void __launch_bounds__(256, 2) gemm_mma(
    const float* __restrict__ A,
    const float* __restrict__ W0, const float* __restrict__ W1, const float* __restrict__ W2,
    const float* __restrict__ b0, const float* __restrict__ b1, const float* __restrict__ b2,
    float* __restrict__ C0, float* __restrict__ C1, float* __restrict__ C2)
{
    constexpr int MI      = BMt / 32;            // 4 or 2
    constexpr int A_FL    = BMt * SA;
    constexpr int STG_FL  = A_FL + B_FLOATS;
    constexpr int STG_B   = STG_FL * 4;
    constexpr int ACH     = BMt * 8 / 256;       // A 16B-chunks per thread

    extern __shared__ char smem[];
    uint32_t sbase;
    asm("{ .reg .u64 t; cvta.to.shared.u64 t, %1; cvt.u32.u64 %0, t; }" : "=r"(sbase) : "l"(smem));

    const int z = blockIdx.z;
    const float* W    = (z == 0) ? W0 : (z == 1) ? W1 : W2;
    const float* bias = (z == 0) ? b0 : (z == 1) ? b1 : b2;
    float*       C    = (z == 0) ? C0 : (z == 1) ? C1 : C2;

    const int tid  = threadIdx.x;
    const int lane = tid & 31;
    const int g    = lane >> 2;
    const int t    = lane & 3;
    const int warp = tid >> 5;
    const int mrow0 = (warp >> 2) * (BMt / 2);
    const int ncol0 = (warp & 3) * 32;
    const int bm = blockIdx.y * BMt;
    const int bn = blockIdx.x * BN;

    float acc[MI][4][4];
#pragma unroll
    for (int i = 0; i < MI; i++)
#pragma unroll
        for (int j = 0; j < 4; j++)
#pragma unroll
            for (int e = 0; e < 4; e++) acc[i][j][e] = 0.0f;

    auto fill = [&](int it) {
        const uint32_t ab = sbase + (uint32_t)((it % NS) * STG_B);
        const uint32_t bb = ab + A_FL * 4;
        const int kt = it * BK;
        const float* Ag = A + (size_t)bm * DM + kt;
        const float* Wg = W + (size_t)kt * DM + bn;
#pragma unroll
        for (int l = 0; l < ACH; l++) {
            int i = tid + l * 256;
            int r = i >> 3, c = i & 7;
            cp16(ab + (uint32_t)(r * (SA * 4) + c * 16), Ag + (size_t)r * DM + c * 4);
        }
#pragma unroll
        for (int l = 0; l < 4; l++) {
            int i = tid + l * 256;
            int r = i >> 5, c = i & 31;
            cp16(bb + (uint32_t)(r * (SB * 4) + c * 16), Wg + (size_t)r * DM + c * 4);
        }
        asm volatile("cp.async.commit_group;" ::: "memory");
    };

    fill(0);
    fill(1);

#pragma unroll 1
    for (int it = 0; it < NK; it++) {
        if (it < NK - 1) asm volatile("cp.async.wait_group 1;" ::: "memory");
        else             asm volatile("cp.async.wait_group 0;" ::: "memory");
        __syncthreads();                     // single barrier per iteration
        if (it + 2 < NK) fill(it + 2);       // prefetch overlaps the MMAs below

        const uint32_t* au = reinterpret_cast<const uint32_t*>(smem) + (it % NS) * STG_FL;
        const uint32_t* bu = au + A_FL;

#pragma unroll
        for (int kk = 0; kk < BK; kk += 8) {
            uint32_t af[MI][4], bf[4][2];
#pragma unroll
            for (int mi = 0; mi < MI; mi++) {
                const int r0 = mrow0 + mi * 16 + g;
                af[mi][0] = au[(r0)     * SA + kk + t];
                af[mi][1] = au[(r0 + 8) * SA + kk + t];
                af[mi][2] = au[(r0)     * SA + kk + t + 4];
                af[mi][3] = au[(r0 + 8) * SA + kk + t + 4];
            }
#pragma unroll
            for (int nj = 0; nj < 4; nj++) {
                const int c = ncol0 + nj * 8 + g;
                bf[nj][0] = bu[(kk + t)     * SB + c];
                bf[nj][1] = bu[(kk + t + 4) * SB + c];
            }
#pragma unroll
            for (int mi = 0; mi < MI; mi++)
#pragma unroll
                for (int nj = 0; nj < 4; nj++)
                    mma_tf32(acc[mi][nj], af[mi], bf[nj]);
        }
    }

    // ---- epilogue: stage accumulators to smem, fused bias, coalesced stores ----
    __syncthreads();
    float* Cs = reinterpret_cast<float*>(smem);
#pragma unroll
    for (int mi = 0; mi < MI; mi++) {
        const int r0 = mrow0 + mi * 16 + g;
#pragma unroll
        for (int nj = 0; nj < 4; nj++) {
            const int c = ncol0 + nj * 8 + 2 * t;
            *reinterpret_cast<float2*>(&Cs[(r0)     * SC + c]) = make_float2(acc[mi][nj][0], acc[mi][nj][1]);
            *reinterpret_cast<float2*>(&Cs[(r0 + 8) * SC + c]) = make_float2(acc[mi][nj][2], acc[mi][nj][3]);
        }
    }
    __syncthreads();

#pragma unroll
    for (int l = 0; l < BMt / 8; l++) {          // BMt x 128 = BMt*32 float4
        int i = tid + l * 256;
        int r = i >> 5, c = (i & 31) * 4;
        float4 v  = *reinterpret_cast<float4*>(&Cs[r * SC + c]);
        float4 bb = *reinterpret_cast<const float4*>(&bias[bn + c]);
        v.x += bb.x; v.y += bb.y; v.z += bb.z; v.w += bb.w;
        *reinterpret_cast<float4*>(&C[(size_t)(bm + r) * DM + bn + c]) = v;
    }
}

// ---------------------------------------------------------------------------
// Rounding passes
// ---------------------------------------------------------------------------
__global__ void round_kernel(const float* __restrict__ src, float* __restrict__ dst, int n4)
{
    int i = blockIdx.x * blockDim.x + threadIdx.x;
    if (i < n4) {
        float4 v = reinterpret_cast<const float4*>(src)[i];
        v.x = tf32_rna(v.x); v.y = tf32_rna(v.y); v.z = tf32_rna(v.z); v.w = tf32_rna(v.w);
        reinterpret_cast<float4*>(dst)[i] = v;
    }
}

__global__ void round_w_kernel(
    const float* __restrict__ W0, const float* __restrict__ W1,
    const float* __restrict__ W2, const float* __restrict__ W3)
{
    const int zz = blockIdx.y;
    const float* src = (zz == 0) ? W0 : (zz == 1) ? W1 : (zz == 2) ? W2 : W3;
    float* dst = g_wr + (size_t)zz * DM * DM;
    const int n4 = DM * DM / 4;
    const int stride = gridDim.x * blockDim.x;
    for (int i = blockIdx.x * blockDim.x + threadIdx.x; i < n4; i += stride) {
        float4 v = reinterpret_cast<const float4*>(src)[i];
        v.x = tf32_rna(v.x); v.y = tf32_rna(v.y); v.z = tf32_rna(v.z); v.w = tf32_rna(v.w);
        reinterpret_cast<float4*>(dst)[i] = v;
    }
}

// ---------------------------------------------------------------------------
// Per-token head-mixing attention, packed f32x2 math (exp-safe scores).
// ---------------------------------------------------------------------------
__global__ void __launch_bounds__(256) attn_kernel()
{
    const int tk = blockIdx.x;
    const int h  = threadIdx.x;

    __shared__ uint64_t sk[NHEADS * 4];
    __shared__ uint64_t sv[NHEADS * 4];

    const uint64_t* qp = reinterpret_cast<const uint64_t*>(&g_q[(size_t)tk * DM]);
    const uint64_t* kp = reinterpret_cast<const uint64_t*>(&g_k[(size_t)tk * DM]);
    const uint64_t* vp = reinterpret_cast<const uint64_t*>(&g_v[(size_t)tk * DM]);

    const float scale = 0.35355339059327373f;   // 1/sqrt(8)
    const uint64_t scl = pk2(scale, scale);

    uint64_t q[4];
#pragma unroll
    for (int j = 0; j < 4; j++) {
        sk[h * 4 + j] = kp[h * 4 + j];
        sv[h * 4 + j] = vp[h * 4 + j];
        q[j] = mul2(qp[h * 4 + j], scl);        // fold 1/sqrt(8) into q
    }
    __syncthreads();

    float lsum = 0.0f;
    uint64_t a[4] = {0ull, 0ull, 0ull, 0ull};   // bit pattern 0 == (0.f, 0.f)

#pragma unroll 8
    for (int gg = 0; gg < NHEADS; gg++) {
        uint64_t pr = mul2(q[0], sk[gg * 4 + 0]);
        pr = fma2(q[1], sk[gg * 4 + 1], pr);
        pr = fma2(q[2], sk[gg * 4 + 2], pr);
        pr = fma2(q[3], sk[gg * 4 + 3], pr);
        float lo, hi; up2(pr, lo, hi);
        float p = __expf(lo + hi);
        lsum += p;
        uint64_t pp = pk2(p, p);
        a[0] = fma2(pp, sv[gg * 4 + 0], a[0]);
        a[1] = fma2(pp, sv[gg * 4 + 1], a[1]);
        a[2] = fma2(pp, sv[gg * 4 + 2], a[2]);
        a[3] = fma2(pp, sv[gg * 4 + 3], a[3]);
    }

    const float inv = 1.0f / lsum;
    float* op = &g_a[(size_t)tk * DM + h * 8];
#pragma unroll
    for (int j = 0; j < 4; j++) {
        float lo, hi; up2(a[j], lo, hi);
        op[2 * j]     = tf32_rna(lo * inv);
        op[2 * j + 1] = tf32_rna(hi * inv);
    }
}

// ---------------------------------------------------------------------------
// Launch
// ---------------------------------------------------------------------------
extern "C" void kernel_launch(void* const* d_in, const int* in_sizes, int n_in,
                              void* d_out, int out_size)
{
    const float* x  = (const float*)d_in[0];
    // d_in[1] = phase_shift: cos^2+sin^2 cancels analytically; unused.
    const float* Wq = (const float*)d_in[2];
    const float* bq = (const float*)d_in[3];
    const float* Wk = (const float*)d_in[4];
    const float* bk = (const float*)d_in[5];
    const float* Wv = (const float*)d_in[6];
    const float* bv = (const float*)d_in[7];
    const float* Wo = (const float*)d_in[8];
    const float* bo = (const float*)d_in[9];
    float* out = (float*)d_out;

    float *q_p, *k_p, *v_p, *a_p, *xr_p, *wr_p;
    cudaGetSymbolAddress((void**)&q_p,  g_q);
    cudaGetSymbolAddress((void**)&k_p,  g_k);
    cudaGetSymbolAddress((void**)&v_p,  g_v);
    cudaGetSymbolAddress((void**)&a_p,  g_a);
    cudaGetSymbolAddress((void**)&xr_p, g_xr);
    cudaGetSymbolAddress((void**)&wr_p, g_wr);

    constexpr int SM128 = NS * (128 * SA + B_FLOATS) * 4;   // 107520
    constexpr int SM64  = NS * (64  * SA + B_FLOATS) * 4;   // 79872
    cudaFuncSetAttribute(gemm_mma<128>, cudaFuncAttributeMaxDynamicSharedMemorySize, SM128);
    cudaFuncSetAttribute(gemm_mma<64>,  cudaFuncAttributeMaxDynamicSharedMemorySize, SM64);

    const size_t WSZ = (size_t)DM * DM;
    const int nx4 = TOKENS * DM / 4;
    round_kernel<<<(nx4 + 255) / 256, 256>>>(x, xr_p, nx4);
    round_w_kernel<<<dim3(512, 4), 256>>>(Wq, Wk, Wv, Wo);

    dim3 gQKV(DM / BN, TOKENS / 128, 3);   // (16, 8, 3)
    gemm_mma<128><<<gQKV, 256, SM128>>>(xr_p,
        wr_p, wr_p + WSZ, wr_p + 2 * WSZ,
        bq, bk, bv, q_p, k_p, v_p);

    attn_kernel<<<TOKENS, 256>>>();

    dim3 gO(DM / BN, TOKENS / 64, 1);      // (16, 16, 1) = 256 CTAs
    gemm_mma<64><<<gO, 256, SM64>>>(a_p,
        wr_p + 3 * WSZ, wr_p + 3 * WSZ, wr_p + 3 * WSZ,
        bo, bo, bo, out, out, out);
}

// round 7
// speedup vs baseline: 2.1452x; 1.0602x over previous
#include <cuda_runtime.h>
#include <cstdint>

// Problem constants: B=4, S=256, D_MODEL=2048, H=256, HEAD_DIM=8
#define TOKENS   1024
#define DM       2048
#define NHEADS   256

// ---------------------------------------------------------------------------
// Scratch (__device__ globals; allocation-free rule)
// ---------------------------------------------------------------------------
__device__ float g_q[TOKENS * DM];
__device__ float g_k[TOKENS * DM];
__device__ float g_v[TOKENS * DM];
__device__ float g_a[TOKENS * DM];          // attn out (tf32-rna rounded)
__device__ float g_xr[TOKENS * DM];         // x, tf32-rna rounded

__device__ __forceinline__ float tf32_rna(float x) {
    float y; asm("cvt.rna.tf32.f32 %0, %1;" : "=f"(y) : "f"(x)); return y;
}
__device__ __forceinline__ void cp16(uint32_t saddr, const void* gptr) {
    asm volatile("cp.async.cg.shared.global [%0], [%1], 16;\n" :: "r"(saddr), "l"(gptr));
}
__device__ __forceinline__ void mma_tf32(float* c, const uint32_t* a, const uint32_t* b) {
    asm volatile(
        "mma.sync.aligned.m16n8k8.row.col.f32.tf32.tf32.f32 "
        "{%0,%1,%2,%3}, {%4,%5,%6,%7}, {%8,%9}, {%0,%1,%2,%3};"
        : "+f"(c[0]), "+f"(c[1]), "+f"(c[2]), "+f"(c[3])
        : "r"(a[0]), "r"(a[1]), "r"(a[2]), "r"(a[3]), "r"(b[0]), "r"(b[1]));
}

// packed f32x2 helpers (base-ISA sm_100+)
__device__ __forceinline__ uint64_t pk2(float lo, float hi) {
    uint64_t r; asm("mov.b64 %0, {%1, %2};" : "=l"(r) : "f"(lo), "f"(hi)); return r;
}
__device__ __forceinline__ void up2(uint64_t v, float& lo, float& hi) {
    asm("mov.b64 {%0, %1}, %2;" : "=f"(lo), "=f"(hi) : "l"(v));
}
__device__ __forceinline__ uint64_t fma2(uint64_t a, uint64_t b, uint64_t c) {
    uint64_t d; asm("fma.rn.f32x2 %0, %1, %2, %3;" : "=l"(d) : "l"(a), "l"(b), "l"(c)); return d;
}
__device__ __forceinline__ uint64_t mul2(uint64_t a, uint64_t b) {
    uint64_t d; asm("mul.rn.f32x2 %0, %1, %2;" : "=l"(d) : "l"(a), "l"(b)); return d;
}

// ---------------------------------------------------------------------------
// TF32 mma.sync GEMM with INLINE W rounding:
//   C[1024,2048] = A @ rna(W) + bias.   A pre-rounded; W raw [K,N] row-major.
// A: 3-stage cp.async ring.  B: LDG.128 -> cvt.rna -> STS.128 (1-reg buffer).
// ---------------------------------------------------------------------------
#define BN 128
#define BK 32
#define NS 3
#define NK (DM / BK)              // 64
#define SA 36                     // A smem row stride (floats)
#define SB 136                    // B smem row stride (floats)
#define B_FLOATS (BK * SB)        // 4352
#define SC 132                    // epilogue staging stride

template <int BMt>
__global__ void __launch_bounds__(256, 2) gemm_mma(
    const float* __restrict__ A,
    const float* __restrict__ W0, const float* __restrict__ W1, const float* __restrict__ W2,
    const float* __restrict__ b0, const float* __restrict__ b1, const float* __restrict__ b2,
    float* __restrict__ C0, float* __restrict__ C1, float* __restrict__ C2)
{
    constexpr int MI      = BMt / 32;            // 4 or 2
    constexpr int A_FL    = BMt * SA;
    constexpr int STG_FL  = A_FL + B_FLOATS;
    constexpr int STG_B   = STG_FL * 4;
    constexpr int ACH     = BMt * 8 / 256;       // A 16B-chunks per thread

    extern __shared__ char smem[];
    uint32_t sbase;
    asm("{ .reg .u64 t; cvta.to.shared.u64 t, %1; cvt.u32.u64 %0, t; }" : "=r"(sbase) : "l"(smem));

    const int z = blockIdx.z;
    const float* W    = (z == 0) ? W0 : (z == 1) ? W1 : W2;
    const float* bias = (z == 0) ? b0 : (z == 1) ? b1 : b2;
    float*       C    = (z == 0) ? C0 : (z == 1) ? C1 : C2;

    const int tid  = threadIdx.x;
    const int lane = tid & 31;
    const int g    = lane >> 2;
    const int t    = lane & 3;
    const int warp = tid >> 5;
    const int mrow0 = (warp >> 2) * (BMt / 2);
    const int ncol0 = (warp & 3) * 32;
    const int bm = blockIdx.y * BMt;
    const int bn = blockIdx.x * BN;

    // B-tile thread mapping: per stage 4 chunks, r = k-row, c = 4-float col
    const int br = tid >> 5;          // 0..7  (k-row base; +8 per chunk l)
    const int bc = (tid & 31) * 4;    // float col 0..124

    float acc[MI][4][4];
#pragma unroll
    for (int i = 0; i < MI; i++)
#pragma unroll
        for (int j = 0; j < 4; j++)
#pragma unroll
            for (int e = 0; e < 4; e++) acc[i][j][e] = 0.0f;

    auto fillA = [&](int it) {
        const uint32_t ab = sbase + (uint32_t)((it % NS) * STG_B);
        const int kt = it * BK;
        const float* Ag = A + (size_t)bm * DM + kt;
#pragma unroll
        for (int l = 0; l < ACH; l++) {
            int i = tid + l * 256;
            int r = i >> 3, c = i & 7;
            cp16(ab + (uint32_t)(r * (SA * 4) + c * 16), Ag + (size_t)r * DM + c * 4);
        }
        asm volatile("cp.async.commit_group;" ::: "memory");
    };

    auto ldgB = [&](int it, float4* breg) {
        const float* Wg = W + (size_t)(it * BK) * DM + bn;
#pragma unroll
        for (int l = 0; l < 4; l++)
            breg[l] = *reinterpret_cast<const float4*>(Wg + (size_t)(br + l * 8) * DM + bc);
    };

    float4 breg[4];
    ldgB(0, breg);
    fillA(0);
    fillA(1);

#pragma unroll 1
    for (int it = 0; it < NK; it++) {
        // STS B(it): round + store (slot free since iter it-3 readers done at bar it-2)
        {
            float* bsm = reinterpret_cast<float*>(smem) + (it % NS) * STG_FL + A_FL;
#pragma unroll
            for (int l = 0; l < 4; l++) {
                float4 v = breg[l];
                v.x = tf32_rna(v.x); v.y = tf32_rna(v.y);
                v.z = tf32_rna(v.z); v.w = tf32_rna(v.w);
                *reinterpret_cast<float4*>(&bsm[(br + l * 8) * SB + bc]) = v;
            }
        }
        if (it + 1 < NK) ldgB(it + 1, breg);     // latency hidden under MMAs below

        if (it < NK - 1) asm volatile("cp.async.wait_group 1;" ::: "memory");
        else             asm volatile("cp.async.wait_group 0;" ::: "memory");
        __syncthreads();
        if (it + 2 < NK) fillA(it + 2);

        const uint32_t* au = reinterpret_cast<const uint32_t*>(smem) + (it % NS) * STG_FL;
        const uint32_t* bu = au + A_FL;

#pragma unroll
        for (int kk = 0; kk < BK; kk += 8) {
            uint32_t af[MI][4], bf[4][2];
#pragma unroll
            for (int mi = 0; mi < MI; mi++) {
                const int r0 = mrow0 + mi * 16 + g;
                af[mi][0] = au[(r0)     * SA + kk + t];
                af[mi][1] = au[(r0 + 8) * SA + kk + t];
                af[mi][2] = au[(r0)     * SA + kk + t + 4];
                af[mi][3] = au[(r0 + 8) * SA + kk + t + 4];
            }
#pragma unroll
            for (int nj = 0; nj < 4; nj++) {
                const int c = ncol0 + nj * 8 + g;
                bf[nj][0] = bu[(kk + t)     * SB + c];
                bf[nj][1] = bu[(kk + t + 4) * SB + c];
            }
#pragma unroll
            for (int mi = 0; mi < MI; mi++)
#pragma unroll
                for (int nj = 0; nj < 4; nj++)
                    mma_tf32(acc[mi][nj], af[mi], bf[nj]);
        }
    }

    // ---- epilogue: stage accumulators to smem, fused bias, coalesced stores ----
    __syncthreads();
    float* Cs = reinterpret_cast<float*>(smem);
#pragma unroll
    for (int mi = 0; mi < MI; mi++) {
        const int r0 = mrow0 + mi * 16 + g;
#pragma unroll
        for (int nj = 0; nj < 4; nj++) {
            const int c = ncol0 + nj * 8 + 2 * t;
            *reinterpret_cast<float2*>(&Cs[(r0)     * SC + c]) = make_float2(acc[mi][nj][0], acc[mi][nj][1]);
            *reinterpret_cast<float2*>(&Cs[(r0 + 8) * SC + c]) = make_float2(acc[mi][nj][2], acc[mi][nj][3]);
        }
    }
    __syncthreads();

#pragma unroll
    for (int l = 0; l < BMt / 8; l++) {
        int i = tid + l * 256;
        int r = i >> 5, c = (i & 31) * 4;
        float4 v  = *reinterpret_cast<float4*>(&Cs[r * SC + c]);
        float4 bb = *reinterpret_cast<const float4*>(&bias[bn + c]);
        v.x += bb.x; v.y += bb.y; v.z += bb.z; v.w += bb.w;
        *reinterpret_cast<float4*>(&C[(size_t)(bm + r) * DM + bn + c]) = v;
    }
}

// ---------------------------------------------------------------------------
// x rounding pass
// ---------------------------------------------------------------------------
__global__ void round_kernel(const float* __restrict__ src, float* __restrict__ dst, int n4)
{
    int i = blockIdx.x * blockDim.x + threadIdx.x;
    if (i < n4) {
        float4 v = reinterpret_cast<const float4*>(src)[i];
        v.x = tf32_rna(v.x); v.y = tf32_rna(v.y); v.z = tf32_rna(v.z); v.w = tf32_rna(v.w);
        reinterpret_cast<float4*>(dst)[i] = v;
    }
}

// ---------------------------------------------------------------------------
// Per-token head-mixing attention: 128 threads, 2 heads/thread (halves LDS).
// ---------------------------------------------------------------------------
__global__ void __launch_bounds__(128) attn_kernel()
{
    const int tk = blockIdx.x;
    const int h0 = threadIdx.x;          // head A
    const int h1 = h0 + 128;             // head B

    __shared__ uint64_t sk[NHEADS * 4];
    __shared__ uint64_t sv[NHEADS * 4];

    const uint64_t* qp = reinterpret_cast<const uint64_t*>(&g_q[(size_t)tk * DM]);
    const uint64_t* kp = reinterpret_cast<const uint64_t*>(&g_k[(size_t)tk * DM]);
    const uint64_t* vp = reinterpret_cast<const uint64_t*>(&g_v[(size_t)tk * DM]);

    const float scale = 0.35355339059327373f;   // 1/sqrt(8)
    const uint64_t scl = pk2(scale, scale);

    uint64_t qa[4], qb[4];
#pragma unroll
    for (int j = 0; j < 4; j++) {
        sk[h0 * 4 + j] = kp[h0 * 4 + j];
        sk[h1 * 4 + j] = kp[h1 * 4 + j];
        sv[h0 * 4 + j] = vp[h0 * 4 + j];
        sv[h1 * 4 + j] = vp[h1 * 4 + j];
        qa[j] = mul2(qp[h0 * 4 + j], scl);
        qb[j] = mul2(qp[h1 * 4 + j], scl);
    }
    __syncthreads();

    float lsa = 0.0f, lsb = 0.0f;
    uint64_t aa[4] = {0ull, 0ull, 0ull, 0ull};
    uint64_t ab[4] = {0ull, 0ull, 0ull, 0ull};

#pragma unroll 4
    for (int gg = 0; gg < NHEADS; gg++) {
        uint64_t k0 = sk[gg * 4 + 0], k1 = sk[gg * 4 + 1];
        uint64_t k2 = sk[gg * 4 + 2], k3 = sk[gg * 4 + 3];

        uint64_t pa = mul2(qa[0], k0);
        pa = fma2(qa[1], k1, pa);
        pa = fma2(qa[2], k2, pa);
        pa = fma2(qa[3], k3, pa);
        uint64_t pb = mul2(qb[0], k0);
        pb = fma2(qb[1], k1, pb);
        pb = fma2(qb[2], k2, pb);
        pb = fma2(qb[3], k3, pb);

        float la, ha, lb, hb;
        up2(pa, la, ha);
        up2(pb, lb, hb);
        float ea = __expf(la + ha);
        float eb = __expf(lb + hb);
        lsa += ea;
        lsb += eb;

        uint64_t v0 = sv[gg * 4 + 0], v1 = sv[gg * 4 + 1];
        uint64_t v2 = sv[gg * 4 + 2], v3 = sv[gg * 4 + 3];
        uint64_t pea = pk2(ea, ea), peb = pk2(eb, eb);
        aa[0] = fma2(pea, v0, aa[0]);  aa[1] = fma2(pea, v1, aa[1]);
        aa[2] = fma2(pea, v2, aa[2]);  aa[3] = fma2(pea, v3, aa[3]);
        ab[0] = fma2(peb, v0, ab[0]);  ab[1] = fma2(peb, v1, ab[1]);
        ab[2] = fma2(peb, v2, ab[2]);  ab[3] = fma2(peb, v3, ab[3]);
    }

    const float inva = 1.0f / lsa;
    const float invb = 1.0f / lsb;
    float* oa = &g_a[(size_t)tk * DM + h0 * 8];
    float* ob = &g_a[(size_t)tk * DM + h1 * 8];
#pragma unroll
    for (int j = 0; j < 4; j++) {
        float lo, hi;
        up2(aa[j], lo, hi);
        oa[2 * j]     = tf32_rna(lo * inva);
        oa[2 * j + 1] = tf32_rna(hi * inva);
        up2(ab[j], lo, hi);
        ob[2 * j]     = tf32_rna(lo * invb);
        ob[2 * j + 1] = tf32_rna(hi * invb);
    }
}

// ---------------------------------------------------------------------------
// Launch
// ---------------------------------------------------------------------------
extern "C" void kernel_launch(void* const* d_in, const int* in_sizes, int n_in,
                              void* d_out, int out_size)
{
    const float* x  = (const float*)d_in[0];
    // d_in[1] = phase_shift: cos^2+sin^2 cancels analytically; unused.
    const float* Wq = (const float*)d_in[2];
    const float* bq = (const float*)d_in[3];
    const float* Wk = (const float*)d_in[4];
    const float* bk = (const float*)d_in[5];
    const float* Wv = (const float*)d_in[6];
    const float* bv = (const float*)d_in[7];
    const float* Wo = (const float*)d_in[8];
    const float* bo = (const float*)d_in[9];
    float* out = (float*)d_out;

    float *q_p, *k_p, *v_p, *a_p, *xr_p;
    cudaGetSymbolAddress((void**)&q_p,  g_q);
    cudaGetSymbolAddress((void**)&k_p,  g_k);
    cudaGetSymbolAddress((void**)&v_p,  g_v);
    cudaGetSymbolAddress((void**)&a_p,  g_a);
    cudaGetSymbolAddress((void**)&xr_p, g_xr);

    constexpr int SM128 = NS * (128 * SA + B_FLOATS) * 4;   // 107520
    constexpr int SM64  = NS * (64  * SA + B_FLOATS) * 4;   // 79872
    cudaFuncSetAttribute(gemm_mma<128>, cudaFuncAttributeMaxDynamicSharedMemorySize, SM128);
    cudaFuncSetAttribute(gemm_mma<64>,  cudaFuncAttributeMaxDynamicSharedMemorySize, SM64);

    const int nx4 = TOKENS * DM / 4;
    round_kernel<<<(nx4 + 255) / 256, 256>>>(x, xr_p, nx4);

    dim3 gQKV(DM / BN, TOKENS / 128, 3);   // (16, 8, 3)
    gemm_mma<128><<<gQKV, 256, SM128>>>(xr_p,
        Wq, Wk, Wv, bq, bk, bv, q_p, k_p, v_p);

    attn_kernel<<<TOKENS, 128>>>();

    dim3 gO(DM / BN, TOKENS / 64, 1);      // (16, 16, 1) = 256 CTAs
    gemm_mma<64><<<gO, 256, SM64>>>(a_p,
        Wo, Wo, Wo, bo, bo, bo, out, out, out);
}

// round 8
// speedup vs baseline: 2.7777x; 1.2948x over previous
#include <cuda_runtime.h>
#include <cuda_fp16.h>
#include <cstdint>

// Problem constants: B=4, S=256, D_MODEL=2048, H=256, HEAD_DIM=8
#define TOKENS   1024
#define DM       2048
#define NHEADS   256

// ---------------------------------------------------------------------------
// Scratch (__device__ globals; allocation-free rule)
// ---------------------------------------------------------------------------
__device__ __align__(16) float  g_q[TOKENS * DM];
__device__ __align__(16) float  g_k[TOKENS * DM];
__device__ __align__(16) float  g_v[TOKENS * DM];
__device__ __align__(16) __half g_ah[TOKENS * DM];      // attn out (fp16)
__device__ __align__(16) __half g_xh[TOKENS * DM];      // x (fp16)
__device__ __align__(16) __half g_wth[4 * DM * DM];     // W^T fp16 (Wq,Wk,Wv,Wo), [N][K]

__device__ __forceinline__ void cp16(uint32_t saddr, const void* gptr) {
    asm volatile("cp.async.cg.shared.global [%0], [%1], 16;\n" :: "r"(saddr), "l"(gptr));
}
__device__ __forceinline__ void mma_f16(float* c, const uint32_t* a, const uint32_t* b) {
    asm volatile(
        "mma.sync.aligned.m16n8k16.row.col.f32.f16.f16.f32 "
        "{%0,%1,%2,%3}, {%4,%5,%6,%7}, {%8,%9}, {%0,%1,%2,%3};"
        : "+f"(c[0]), "+f"(c[1]), "+f"(c[2]), "+f"(c[3])
        : "r"(a[0]), "r"(a[1]), "r"(a[2]), "r"(a[3]), "r"(b[0]), "r"(b[1]));
}

// packed f32x2 helpers (base-ISA sm_100+)
__device__ __forceinline__ uint64_t pk2(float lo, float hi) {
    uint64_t r; asm("mov.b64 %0, {%1, %2};" : "=l"(r) : "f"(lo), "f"(hi)); return r;
}
__device__ __forceinline__ void up2(uint64_t v, float& lo, float& hi) {
    asm("mov.b64 {%0, %1}, %2;" : "=f"(lo), "=f"(hi) : "l"(v));
}
__device__ __forceinline__ uint64_t fma2(uint64_t a, uint64_t b, uint64_t c) {
    uint64_t d; asm("fma.rn.f32x2 %0, %1, %2, %3;" : "=l"(d) : "l"(a), "l"(b), "l"(c)); return d;
}
__device__ __forceinline__ uint64_t mul2(uint64_t a, uint64_t b) {
    uint64_t d; asm("mul.rn.f32x2 %0, %1, %2;" : "=l"(d) : "l"(a), "l"(b)); return d;
}

// ---------------------------------------------------------------------------
// FP16 mma.sync GEMM: C[1024,2048](f32) = A(h)[M,K] @ Wt(h)[N,K]^T + bias(f32)
// CTA 128x128x32, 8 warps (2x4), warp 64x32, 4-stage cp.async ring.
// Both tiles k-contiguous halves, row stride SAh=40 halves (conflict-free).
// ---------------------------------------------------------------------------
#define BM 128
#define BN 128
#define BK 32
#define NS 4
#define NK (DM / BK)              // 64
#define SAH 40                    // halves per row (80 B, 16B-multiple)
#define A_H (BM * SAH)            // 5120 halves
#define STG_H (2 * A_H)           // A tile + B tile
#define STG_B (STG_H * 2)         // 20480 bytes
#define GEMM_SMEM (NS * STG_B)    // 81920 (>= epilogue 128*132*4 = 67584)
#define SC 132                    // epilogue f32 staging stride

__global__ void __launch_bounds__(256, 2) gemm_h(
    const __half* __restrict__ A,
    const __half* __restrict__ T0, const __half* __restrict__ T1, const __half* __restrict__ T2,
    const float* __restrict__ b0, const float* __restrict__ b1, const float* __restrict__ b2,
    float* __restrict__ C0, float* __restrict__ C1, float* __restrict__ C2)
{
    extern __shared__ char smem[];
    uint32_t sbase;
    asm("{ .reg .u64 t; cvta.to.shared.u64 t, %1; cvt.u32.u64 %0, t; }" : "=r"(sbase) : "l"(smem));

    const int z = blockIdx.z;
    const __half* Wt  = (z == 0) ? T0 : (z == 1) ? T1 : T2;
    const float* bias = (z == 0) ? b0 : (z == 1) ? b1 : b2;
    float*       C    = (z == 0) ? C0 : (z == 1) ? C1 : C2;

    const int tid  = threadIdx.x;
    const int lane = tid & 31;
    const int g    = lane >> 2;
    const int t    = lane & 3;
    const int warp = tid >> 5;
    const int mrow0 = (warp >> 2) * 64;
    const int ncol0 = (warp & 3) * 32;
    const int bm = blockIdx.y * BM;
    const int bn = blockIdx.x * BN;

    float acc[4][4][4];
#pragma unroll
    for (int i = 0; i < 4; i++)
#pragma unroll
        for (int j = 0; j < 4; j++)
#pragma unroll
            for (int e = 0; e < 4; e++) acc[i][j][e] = 0.0f;

    auto fill = [&](int it) {
        const uint32_t ab = sbase + (uint32_t)((it % NS) * STG_B);
        const uint32_t bb = ab + A_H * 2;
        const int kt = it * BK;
        const __half* Ag = A  + (size_t)bm * DM + kt;
        const __half* Bg = Wt + (size_t)bn * DM + kt;
#pragma unroll
        for (int l = 0; l < 2; l++) {              // A: 128 rows x 4 chunks(16B)
            int i = tid + l * 256;
            int r = i >> 2, c = i & 3;
            cp16(ab + (uint32_t)(r * 80 + c * 16), Ag + (size_t)r * DM + c * 8);
        }
#pragma unroll
        for (int l = 0; l < 2; l++) {              // B: 128 n-rows x 4 chunks
            int i = tid + l * 256;
            int r = i >> 2, c = i & 3;
            cp16(bb + (uint32_t)(r * 80 + c * 16), Bg + (size_t)r * DM + c * 8);
        }
        asm volatile("cp.async.commit_group;" ::: "memory");
    };

    fill(0); fill(1); fill(2);

#pragma unroll 1
    for (int it = 0; it < NK; it++) {
        asm volatile("cp.async.wait_group 2;" ::: "memory");
        __syncthreads();
        if (it + 3 < NK) fill(it + 3);
        else asm volatile("cp.async.commit_group;" ::: "memory");   // keep group count

        const uint32_t* au = reinterpret_cast<const uint32_t*>(smem + (it % NS) * STG_B);
        const uint32_t* bu = au + A_H / 2;

#pragma unroll
        for (int kk = 0; kk < BK; kk += 16) {
            const int kw = kk >> 1;                // word offset
            uint32_t af[4][4], bf[4][2];
#pragma unroll
            for (int mi = 0; mi < 4; mi++) {
                const int r0 = mrow0 + mi * 16 + g;
                af[mi][0] = au[(r0)     * (SAH/2) + kw + t];
                af[mi][1] = au[(r0 + 8) * (SAH/2) + kw + t];
                af[mi][2] = au[(r0)     * (SAH/2) + kw + t + 4];
                af[mi][3] = au[(r0 + 8) * (SAH/2) + kw + t + 4];
            }
#pragma unroll
            for (int nj = 0; nj < 4; nj++) {
                const int c = ncol0 + nj * 8 + g;
                bf[nj][0] = bu[c * (SAH/2) + kw + t];
                bf[nj][1] = bu[c * (SAH/2) + kw + t + 4];
            }
#pragma unroll
            for (int mi = 0; mi < 4; mi++)
#pragma unroll
                for (int nj = 0; nj < 4; nj++)
                    mma_f16(acc[mi][nj], af[mi], bf[nj]);
        }
    }

    // ---- epilogue: stage accumulators to smem, fused bias, coalesced stores ----
    __syncthreads();
    float* Cs = reinterpret_cast<float*>(smem);
#pragma unroll
    for (int mi = 0; mi < 4; mi++) {
        const int r0 = mrow0 + mi * 16 + g;
#pragma unroll
        for (int nj = 0; nj < 4; nj++) {
            const int c = ncol0 + nj * 8 + 2 * t;
            *reinterpret_cast<float2*>(&Cs[(r0)     * SC + c]) = make_float2(acc[mi][nj][0], acc[mi][nj][1]);
            *reinterpret_cast<float2*>(&Cs[(r0 + 8) * SC + c]) = make_float2(acc[mi][nj][2], acc[mi][nj][3]);
        }
    }
    __syncthreads();

#pragma unroll
    for (int l = 0; l < 16; l++) {
        int i = tid + l * 256;
        int r = i >> 5, c = (i & 31) * 4;
        float4 v  = *reinterpret_cast<float4*>(&Cs[r * SC + c]);
        float4 bb = *reinterpret_cast<const float4*>(&bias[bn + c]);
        v.x += bb.x; v.y += bb.y; v.z += bb.z; v.w += bb.w;
        *reinterpret_cast<float4*>(&C[(size_t)(bm + r) * DM + bn + c]) = v;
    }
}

// ---------------------------------------------------------------------------
// Prep: x -> half;  W[k][n] f32 -> Wt[n][k] half (transpose + convert)
// ---------------------------------------------------------------------------
__global__ void xcvt_kernel(const float* __restrict__ src, __half* __restrict__ dst, int n4)
{
    int i = blockIdx.x * blockDim.x + threadIdx.x;
    if (i < n4) {
        float4 v = reinterpret_cast<const float4*>(src)[i];
        __half2* d = reinterpret_cast<__half2*>(dst) + 2 * i;
        d[0] = __floats2half2_rn(v.x, v.y);
        d[1] = __floats2half2_rn(v.z, v.w);
    }
}

__global__ void wtrans_kernel(
    const float* __restrict__ W0, const float* __restrict__ W1,
    const float* __restrict__ W2, const float* __restrict__ W3)
{
    __shared__ float tsm[32][33];
    const int zz = blockIdx.z;
    const float* src = (zz == 0) ? W0 : (zz == 1) ? W1 : (zz == 2) ? W2 : W3;
    __half* dst = g_wth + (size_t)zz * DM * DM;

    const int n0 = blockIdx.x * 32;
    const int k0 = blockIdx.y * 32;
    const int tid = threadIdx.x;           // 256 threads
    const int tx = tid & 31, ty = tid >> 5;

#pragma unroll
    for (int j = ty; j < 32; j += 8)       // load: k-rows, n contiguous
        tsm[j][tx] = src[(size_t)(k0 + j) * DM + n0 + tx];
    __syncthreads();

    // store: n-rows, k contiguous as half2 (32 rows x 16 half2)
#pragma unroll
    for (int idx = tid; idx < 32 * 16; idx += 256) {
        int r = idx >> 4, c = idx & 15;
        __half2 h = __floats2half2_rn(tsm[2 * c][r], tsm[2 * c + 1][r]);
        *reinterpret_cast<__half2*>(&dst[(size_t)(n0 + r) * DM + k0 + 2 * c]) = h;
    }
}

// ---------------------------------------------------------------------------
// Per-token head-mixing attention: 128 threads, 2 heads/thread, f32x2 math.
// Output written as fp16 (it is the O-GEMM's A operand).
// ---------------------------------------------------------------------------
__global__ void __launch_bounds__(128) attn_kernel()
{
    const int tk = blockIdx.x;
    const int h0 = threadIdx.x;
    const int h1 = h0 + 128;

    __shared__ uint64_t sk[NHEADS * 4];
    __shared__ uint64_t sv[NHEADS * 4];

    const uint64_t* qp = reinterpret_cast<const uint64_t*>(&g_q[(size_t)tk * DM]);
    const uint64_t* kp = reinterpret_cast<const uint64_t*>(&g_k[(size_t)tk * DM]);
    const uint64_t* vp = reinterpret_cast<const uint64_t*>(&g_v[(size_t)tk * DM]);

    const float scale = 0.35355339059327373f;   // 1/sqrt(8)
    const uint64_t scl = pk2(scale, scale);

    uint64_t qa[4], qb[4];
#pragma unroll
    for (int j = 0; j < 4; j++) {
        sk[h0 * 4 + j] = kp[h0 * 4 + j];
        sk[h1 * 4 + j] = kp[h1 * 4 + j];
        sv[h0 * 4 + j] = vp[h0 * 4 + j];
        sv[h1 * 4 + j] = vp[h1 * 4 + j];
        qa[j] = mul2(qp[h0 * 4 + j], scl);
        qb[j] = mul2(qp[h1 * 4 + j], scl);
    }
    __syncthreads();

    float lsa = 0.0f, lsb = 0.0f;
    uint64_t aa[4] = {0ull, 0ull, 0ull, 0ull};
    uint64_t ab[4] = {0ull, 0ull, 0ull, 0ull};

#pragma unroll 4
    for (int gg = 0; gg < NHEADS; gg++) {
        uint64_t k0 = sk[gg * 4 + 0], k1 = sk[gg * 4 + 1];
        uint64_t k2 = sk[gg * 4 + 2], k3 = sk[gg * 4 + 3];

        uint64_t pa = mul2(qa[0], k0);
        pa = fma2(qa[1], k1, pa);
        pa = fma2(qa[2], k2, pa);
        pa = fma2(qa[3], k3, pa);
        uint64_t pb = mul2(qb[0], k0);
        pb = fma2(qb[1], k1, pb);
        pb = fma2(qb[2], k2, pb);
        pb = fma2(qb[3], k3, pb);

        float la, ha, lb, hb;
        up2(pa, la, ha);
        up2(pb, lb, hb);
        float ea = __expf(la + ha);
        float eb = __expf(lb + hb);
        lsa += ea;
        lsb += eb;

        uint64_t v0 = sv[gg * 4 + 0], v1 = sv[gg * 4 + 1];
        uint64_t v2 = sv[gg * 4 + 2], v3 = sv[gg * 4 + 3];
        uint64_t pea = pk2(ea, ea), peb = pk2(eb, eb);
        aa[0] = fma2(pea, v0, aa[0]);  aa[1] = fma2(pea, v1, aa[1]);
        aa[2] = fma2(pea, v2, aa[2]);  aa[3] = fma2(pea, v3, aa[3]);
        ab[0] = fma2(peb, v0, ab[0]);  ab[1] = fma2(peb, v1, ab[1]);
        ab[2] = fma2(peb, v2, ab[2]);  ab[3] = fma2(peb, v3, ab[3]);
    }

    const float inva = 1.0f / lsa;
    const float invb = 1.0f / lsb;
    __half2* oa = reinterpret_cast<__half2*>(&g_ah[(size_t)tk * DM + h0 * 8]);
    __half2* ob = reinterpret_cast<__half2*>(&g_ah[(size_t)tk * DM + h1 * 8]);
#pragma unroll
    for (int j = 0; j < 4; j++) {
        float lo, hi;
        up2(aa[j], lo, hi);
        oa[j] = __floats2half2_rn(lo * inva, hi * inva);
        up2(ab[j], lo, hi);
        ob[j] = __floats2half2_rn(lo * invb, hi * invb);
    }
}

// ---------------------------------------------------------------------------
// Launch
// ---------------------------------------------------------------------------
extern "C" void kernel_launch(void* const* d_in, const int* in_sizes, int n_in,
                              void* d_out, int out_size)
{
    const float* x  = (const float*)d_in[0];
    // d_in[1] = phase_shift: cos^2+sin^2 cancels analytically; unused.
    const float* Wq = (const float*)d_in[2];
    const float* bq = (const float*)d_in[3];
    const float* Wk = (const float*)d_in[4];
    const float* bk = (const float*)d_in[5];
    const float* Wv = (const float*)d_in[6];
    const float* bv = (const float*)d_in[7];
    const float* Wo = (const float*)d_in[8];
    const float* bo = (const float*)d_in[9];
    float* out = (float*)d_out;

    float *q_p, *k_p, *v_p;
    __half *ah_p, *xh_p, *wt_p;
    cudaGetSymbolAddress((void**)&q_p,  g_q);
    cudaGetSymbolAddress((void**)&k_p,  g_k);
    cudaGetSymbolAddress((void**)&v_p,  g_v);
    cudaGetSymbolAddress((void**)&ah_p, g_ah);
    cudaGetSymbolAddress((void**)&xh_p, g_xh);
    cudaGetSymbolAddress((void**)&wt_p, g_wth);

    cudaFuncSetAttribute(gemm_h, cudaFuncAttributeMaxDynamicSharedMemorySize, GEMM_SMEM);

    const size_t WSZ = (size_t)DM * DM;
    const int nx4 = TOKENS * DM / 4;
    xcvt_kernel<<<(nx4 + 255) / 256, 256>>>(x, xh_p, nx4);
    wtrans_kernel<<<dim3(DM / 32, DM / 32, 4), 256>>>(Wq, Wk, Wv, Wo);

    dim3 gQKV(DM / BN, TOKENS / BM, 3);    // (16, 8, 3)
    gemm_h<<<gQKV, 256, GEMM_SMEM>>>(xh_p,
        wt_p, wt_p + WSZ, wt_p + 2 * WSZ,
        bq, bk, bv, q_p, k_p, v_p);

    attn_kernel<<<TOKENS, 128>>>();

    dim3 gO(DM / BN, TOKENS / BM, 1);      // (16, 8, 1)
    gemm_h<<<gO, 256, GEMM_SMEM>>>(ah_p,
        wt_p + 3 * WSZ, wt_p + 3 * WSZ, wt_p + 3 * WSZ,
        bo, bo, bo, out, out, out);
}

// round 9
// speedup vs baseline: 2.9726x; 1.0701x over previous
#include <cuda_runtime.h>
#include <cuda_fp16.h>
#include <cstdint>

// Problem constants: B=4, S=256, D_MODEL=2048, H=256, HEAD_DIM=8
#define TOKENS   1024
#define DM       2048
#define NHEADS   256

// ---------------------------------------------------------------------------
// Scratch (__device__ globals; allocation-free rule)
// ---------------------------------------------------------------------------
__device__ __align__(16) float  g_q[TOKENS * DM];
__device__ __align__(16) float  g_k[TOKENS * DM];
__device__ __align__(16) float  g_v[TOKENS * DM];
__device__ __align__(16) __half g_ah[TOKENS * DM];      // attn out (fp16)
__device__ __align__(16) __half g_xh[TOKENS * DM];      // x (fp16)
__device__ __align__(16) __half g_wth[4 * DM * DM];     // W^T fp16 (Wq,Wk,Wv,Wo), [N][K]

__device__ __forceinline__ void cp16(uint32_t saddr, const void* gptr) {
    asm volatile("cp.async.cg.shared.global [%0], [%1], 16;\n" :: "r"(saddr), "l"(gptr));
}
__device__ __forceinline__ void mma_f16(float* c, const uint32_t* a, const uint32_t* b) {
    asm volatile(
        "mma.sync.aligned.m16n8k16.row.col.f32.f16.f16.f32 "
        "{%0,%1,%2,%3}, {%4,%5,%6,%7}, {%8,%9}, {%0,%1,%2,%3};"
        : "+f"(c[0]), "+f"(c[1]), "+f"(c[2]), "+f"(c[3])
        : "r"(a[0]), "r"(a[1]), "r"(a[2]), "r"(a[3]), "r"(b[0]), "r"(b[1]));
}
__device__ __forceinline__ void ldsm4(uint32_t& r0, uint32_t& r1, uint32_t& r2, uint32_t& r3,
                                      uint32_t addr) {
    asm volatile("ldmatrix.sync.aligned.m8n8.x4.shared.b16 {%0,%1,%2,%3}, [%4];"
                 : "=r"(r0), "=r"(r1), "=r"(r2), "=r"(r3) : "r"(addr));
}

// packed f32x2 helpers (base-ISA sm_100+)
__device__ __forceinline__ uint64_t pk2(float lo, float hi) {
    uint64_t r; asm("mov.b64 %0, {%1, %2};" : "=l"(r) : "f"(lo), "f"(hi)); return r;
}
__device__ __forceinline__ void up2(uint64_t v, float& lo, float& hi) {
    asm("mov.b64 {%0, %1}, %2;" : "=f"(lo), "=f"(hi) : "l"(v));
}
__device__ __forceinline__ uint64_t fma2(uint64_t a, uint64_t b, uint64_t c) {
    uint64_t d; asm("fma.rn.f32x2 %0, %1, %2, %3;" : "=l"(d) : "l"(a), "l"(b), "l"(c)); return d;
}
__device__ __forceinline__ uint64_t mul2(uint64_t a, uint64_t b) {
    uint64_t d; asm("mul.rn.f32x2 %0, %1, %2;" : "=l"(d) : "l"(a), "l"(b)); return d;
}
__device__ __forceinline__ float ex2f(float x) {
    float y; asm("ex2.approx.f32 %0, %1;" : "=f"(y) : "f"(x)); return y;
}

// ---------------------------------------------------------------------------
// FP16 mma.sync GEMM: C[1024,2048](f32) = A(h)[M,K] @ Wt(h)[N,K]^T + bias(f32)
// CTA 128x128x32, 8 warps (2x4), warp 64x32, 4-stage cp.async ring.
// Fragments loaded via ldmatrix (LDSM.x4): 6 LDSM + 16 HMMA per k16 step.
// ---------------------------------------------------------------------------
#define BM 128
#define BN 128
#define BK 32
#define NS 4
#define NK (DM / BK)              // 64
#define SAH 40                    // halves per row (80 B, 16B multiple, LDSM conflict-free)
#define A_H (BM * SAH)            // 5120 halves
#define STG_B (4 * A_H)           // 20480 bytes (A tile + B tile)
#define GEMM_SMEM (NS * STG_B)    // 81920 (>= epilogue 128*132*4 = 67584)
#define SC 132                    // epilogue f32 staging stride

__global__ void __launch_bounds__(256, 2) gemm_h(
    const __half* __restrict__ A,
    const __half* __restrict__ T0, const __half* __restrict__ T1, const __half* __restrict__ T2,
    const float* __restrict__ b0, const float* __restrict__ b1, const float* __restrict__ b2,
    float* __restrict__ C0, float* __restrict__ C1, float* __restrict__ C2)
{
    extern __shared__ char smem[];
    uint32_t sbase;
    asm("{ .reg .u64 t; cvta.to.shared.u64 t, %1; cvt.u32.u64 %0, t; }" : "=r"(sbase) : "l"(smem));

    const int z = blockIdx.z;
    const __half* Wt  = (z == 0) ? T0 : (z == 1) ? T1 : T2;
    const float* bias = (z == 0) ? b0 : (z == 1) ? b1 : b2;
    float*       C    = (z == 0) ? C0 : (z == 1) ? C1 : C2;

    const int tid  = threadIdx.x;
    const int lane = tid & 31;
    const int g    = lane >> 2;
    const int t    = lane & 3;
    const int warp = tid >> 5;
    const int mrow0 = (warp >> 2) * 64;
    const int ncol0 = (warp & 3) * 32;
    const int bm = blockIdx.y * BM;
    const int bn = blockIdx.x * BN;

    // ldmatrix per-lane base offsets (halves):
    // A tile (x4 per mi): row = mrow0 + mi*16 + (lane&15), col = kk + (lane>>4)*8
    const uint32_t a_lm = (uint32_t)((mrow0 + (lane & 15)) * SAH + (lane >> 4) * 8);
    // B tile (x4 per nj-pair p): row = ncol0 + p*16 + (lane>>4)*8 + (lane&7),
    //                            col = kk + ((lane>>3)&1)*8
    const uint32_t b_lm = (uint32_t)((ncol0 + (lane >> 4) * 8 + (lane & 7)) * SAH
                                     + ((lane >> 3) & 1) * 8);

    float acc[4][4][4];
#pragma unroll
    for (int i = 0; i < 4; i++)
#pragma unroll
        for (int j = 0; j < 4; j++)
#pragma unroll
            for (int e = 0; e < 4; e++) acc[i][j][e] = 0.0f;

    auto fill = [&](int it) {
        const uint32_t ab = sbase + (uint32_t)((it % NS) * STG_B);
        const uint32_t bb = ab + A_H * 2;
        const int kt = it * BK;
        const __half* Ag = A  + (size_t)bm * DM + kt;
        const __half* Bg = Wt + (size_t)bn * DM + kt;
#pragma unroll
        for (int l = 0; l < 2; l++) {
            int i = tid + l * 256;
            int r = i >> 2, c = i & 3;
            cp16(ab + (uint32_t)(r * 80 + c * 16), Ag + (size_t)r * DM + c * 8);
        }
#pragma unroll
        for (int l = 0; l < 2; l++) {
            int i = tid + l * 256;
            int r = i >> 2, c = i & 3;
            cp16(bb + (uint32_t)(r * 80 + c * 16), Bg + (size_t)r * DM + c * 8);
        }
        asm volatile("cp.async.commit_group;" ::: "memory");
    };

    fill(0); fill(1); fill(2);

#pragma unroll 1
    for (int it = 0; it < NK; it++) {
        asm volatile("cp.async.wait_group 2;" ::: "memory");
        __syncthreads();
        if (it + 3 < NK) fill(it + 3);
        else asm volatile("cp.async.commit_group;" ::: "memory");

        const uint32_t abase = sbase + (uint32_t)((it % NS) * STG_B);
        const uint32_t bbase = abase + A_H * 2;

#pragma unroll
        for (int kk = 0; kk < BK; kk += 16) {
            uint32_t af[4][4], bf[4][2];
#pragma unroll
            for (int mi = 0; mi < 4; mi++)
                ldsm4(af[mi][0], af[mi][1], af[mi][2], af[mi][3],
                      abase + (a_lm + (uint32_t)(mi * 16 * SAH + kk)) * 2);
#pragma unroll
            for (int p = 0; p < 2; p++)
                ldsm4(bf[2*p][0], bf[2*p][1], bf[2*p+1][0], bf[2*p+1][1],
                      bbase + (b_lm + (uint32_t)(p * 16 * SAH + kk)) * 2);
#pragma unroll
            for (int mi = 0; mi < 4; mi++)
#pragma unroll
                for (int nj = 0; nj < 4; nj++)
                    mma_f16(acc[mi][nj], af[mi], bf[nj]);
        }
    }

    // ---- epilogue: stage accumulators to smem, fused bias, coalesced stores ----
    __syncthreads();
    float* Cs = reinterpret_cast<float*>(smem);
#pragma unroll
    for (int mi = 0; mi < 4; mi++) {
        const int r0 = mrow0 + mi * 16 + g;
#pragma unroll
        for (int nj = 0; nj < 4; nj++) {
            const int c = ncol0 + nj * 8 + 2 * t;
            *reinterpret_cast<float2*>(&Cs[(r0)     * SC + c]) = make_float2(acc[mi][nj][0], acc[mi][nj][1]);
            *reinterpret_cast<float2*>(&Cs[(r0 + 8) * SC + c]) = make_float2(acc[mi][nj][2], acc[mi][nj][3]);
        }
    }
    __syncthreads();

#pragma unroll
    for (int l = 0; l < 16; l++) {
        int i = tid + l * 256;
        int r = i >> 5, c = (i & 31) * 4;
        float4 v  = *reinterpret_cast<float4*>(&Cs[r * SC + c]);
        float4 bb = *reinterpret_cast<const float4*>(&bias[bn + c]);
        v.x += bb.x; v.y += bb.y; v.z += bb.z; v.w += bb.w;
        *reinterpret_cast<float4*>(&C[(size_t)(bm + r) * DM + bn + c]) = v;
    }
}

// ---------------------------------------------------------------------------
// Prep: x -> half;  W[k][n] f32 -> Wt[n][k] half (transpose + convert)
// ---------------------------------------------------------------------------
__global__ void xcvt_kernel(const float* __restrict__ src, __half* __restrict__ dst, int n4)
{
    int i = blockIdx.x * blockDim.x + threadIdx.x;
    if (i < n4) {
        float4 v = reinterpret_cast<const float4*>(src)[i];
        __half2* d = reinterpret_cast<__half2*>(dst) + 2 * i;
        d[0] = __floats2half2_rn(v.x, v.y);
        d[1] = __floats2half2_rn(v.z, v.w);
    }
}

__global__ void wtrans_kernel(
    const float* __restrict__ W0, const float* __restrict__ W1,
    const float* __restrict__ W2, const float* __restrict__ W3)
{
    __shared__ float tsm[32][33];
    const int zz = blockIdx.z;
    const float* src = (zz == 0) ? W0 : (zz == 1) ? W1 : (zz == 2) ? W2 : W3;
    __half* dst = g_wth + (size_t)zz * DM * DM;

    const int n0 = blockIdx.x * 32;
    const int k0 = blockIdx.y * 32;
    const int tid = threadIdx.x;
    const int tx = tid & 31, ty = tid >> 5;

#pragma unroll
    for (int j = ty; j < 32; j += 8)
        tsm[j][tx] = src[(size_t)(k0 + j) * DM + n0 + tx];
    __syncthreads();

#pragma unroll
    for (int idx = tid; idx < 32 * 16; idx += 256) {
        int r = idx >> 4, c = idx & 15;
        __half2 h = __floats2half2_rn(tsm[2 * c][r], tsm[2 * c + 1][r]);
        *reinterpret_cast<__half2*>(&dst[(size_t)(n0 + r) * DM + k0 + 2 * c]) = h;
    }
}

// ---------------------------------------------------------------------------
// Per-token head-mixing attention: 128 threads, 2 heads/thread, f32x2 + ex2.
// q pre-scaled by log2(e)/sqrt(8) so softmax exp is a bare ex2.approx.
// ---------------------------------------------------------------------------
__global__ void __launch_bounds__(128) attn_kernel()
{
    const int tk = blockIdx.x;
    const int h0 = threadIdx.x;
    const int h1 = h0 + 128;

    __shared__ uint64_t sk[NHEADS * 4];
    __shared__ uint64_t sv[NHEADS * 4];

    const uint64_t* qp = reinterpret_cast<const uint64_t*>(&g_q[(size_t)tk * DM]);
    const uint64_t* kp = reinterpret_cast<const uint64_t*>(&g_k[(size_t)tk * DM]);
    const uint64_t* vp = reinterpret_cast<const uint64_t*>(&g_v[(size_t)tk * DM]);

    const float scale = 0.35355339059327373f * 1.4426950408889634f;  // log2e/sqrt(8)
    const uint64_t scl = pk2(scale, scale);

    uint64_t qa[4], qb[4];
#pragma unroll
    for (int j = 0; j < 4; j++) {
        sk[h0 * 4 + j] = kp[h0 * 4 + j];
        sk[h1 * 4 + j] = kp[h1 * 4 + j];
        sv[h0 * 4 + j] = vp[h0 * 4 + j];
        sv[h1 * 4 + j] = vp[h1 * 4 + j];
        qa[j] = mul2(qp[h0 * 4 + j], scl);
        qb[j] = mul2(qp[h1 * 4 + j], scl);
    }
    __syncthreads();

    float lsa = 0.0f, lsb = 0.0f;
    uint64_t aa[4] = {0ull, 0ull, 0ull, 0ull};
    uint64_t ab[4] = {0ull, 0ull, 0ull, 0ull};

#pragma unroll 4
    for (int gg = 0; gg < NHEADS; gg++) {
        uint64_t k0 = sk[gg * 4 + 0], k1 = sk[gg * 4 + 1];
        uint64_t k2 = sk[gg * 4 + 2], k3 = sk[gg * 4 + 3];

        uint64_t pa = mul2(qa[0], k0);
        pa = fma2(qa[1], k1, pa);
        pa = fma2(qa[2], k2, pa);
        pa = fma2(qa[3], k3, pa);
        uint64_t pb = mul2(qb[0], k0);
        pb = fma2(qb[1], k1, pb);
        pb = fma2(qb[2], k2, pb);
        pb = fma2(qb[3], k3, pb);

        float la, ha, lb, hb;
        up2(pa, la, ha);
        up2(pb, lb, hb);
        float ea = ex2f(la + ha);      // base-2 exp; log2e folded into q scale
        float eb = ex2f(lb + hb);
        lsa += ea;
        lsb += eb;

        uint64_t v0 = sv[gg * 4 + 0], v1 = sv[gg * 4 + 1];
        uint64_t v2 = sv[gg * 4 + 2], v3 = sv[gg * 4 + 3];
        uint64_t pea = pk2(ea, ea), peb = pk2(eb, eb);
        aa[0] = fma2(pea, v0, aa[0]);  aa[1] = fma2(pea, v1, aa[1]);
        aa[2] = fma2(pea, v2, aa[2]);  aa[3] = fma2(pea, v3, aa[3]);
        ab[0] = fma2(peb, v0, ab[0]);  ab[1] = fma2(peb, v1, ab[1]);
        ab[2] = fma2(peb, v2, ab[2]);  ab[3] = fma2(peb, v3, ab[3]);
    }

    const float inva = 1.0f / lsa;
    const float invb = 1.0f / lsb;
    __half2* oa = reinterpret_cast<__half2*>(&g_ah[(size_t)tk * DM + h0 * 8]);
    __half2* ob = reinterpret_cast<__half2*>(&g_ah[(size_t)tk * DM + h1 * 8]);
#pragma unroll
    for (int j = 0; j < 4; j++) {
        float lo, hi;
        up2(aa[j], lo, hi);
        oa[j] = __floats2half2_rn(lo * inva, hi * inva);
        up2(ab[j], lo, hi);
        ob[j] = __floats2half2_rn(lo * invb, hi * invb);
    }
}

// ---------------------------------------------------------------------------
// Launch
// ---------------------------------------------------------------------------
extern "C" void kernel_launch(void* const* d_in, const int* in_sizes, int n_in,
                              void* d_out, int out_size)
{
    const float* x  = (const float*)d_in[0];
    // d_in[1] = phase_shift: cos^2+sin^2 cancels analytically; unused.
    const float* Wq = (const float*)d_in[2];
    const float* bq = (const float*)d_in[3];
    const float* Wk = (const float*)d_in[4];
    const float* bk = (const float*)d_in[5];
    const float* Wv = (const float*)d_in[6];
    const float* bv = (const float*)d_in[7];
    const float* Wo = (const float*)d_in[8];
    const float* bo = (const float*)d_in[9];
    float* out = (float*)d_out;

    float *q_p, *k_p, *v_p;
    __half *ah_p, *xh_p, *wt_p;
    cudaGetSymbolAddress((void**)&q_p,  g_q);
    cudaGetSymbolAddress((void**)&k_p,  g_k);
    cudaGetSymbolAddress((void**)&v_p,  g_v);
    cudaGetSymbolAddress((void**)&ah_p, g_ah);
    cudaGetSymbolAddress((void**)&xh_p, g_xh);
    cudaGetSymbolAddress((void**)&wt_p, g_wth);

    cudaFuncSetAttribute(gemm_h, cudaFuncAttributeMaxDynamicSharedMemorySize, GEMM_SMEM);

    const size_t WSZ = (size_t)DM * DM;
    const int nx4 = TOKENS * DM / 4;
    xcvt_kernel<<<(nx4 + 255) / 256, 256>>>(x, xh_p, nx4);
    wtrans_kernel<<<dim3(DM / 32, DM / 32, 4), 256>>>(Wq, Wk, Wv, Wo);

    dim3 gQKV(DM / BN, TOKENS / BM, 3);    // (16, 8, 3)
    gemm_h<<<gQKV, 256, GEMM_SMEM>>>(xh_p,
        wt_p, wt_p + WSZ, wt_p + 2 * WSZ,
        bq, bk, bv, q_p, k_p, v_p);

    attn_kernel<<<TOKENS, 128>>>();

    dim3 gO(DM / BN, TOKENS / BM, 1);      // (16, 8, 1)
    gemm_h<<<gO, 256, GEMM_SMEM>>>(ah_p,
        wt_p + 3 * WSZ, wt_p + 3 * WSZ, wt_p + 3 * WSZ,
        bo, bo, bo, out, out, out);
}